// round 7
// baseline (speedup 1.0000x reference)
#include <cuda_runtime.h>
#include <cuda_fp16.h>
#include <cstdint>
#include <mma.h>
using namespace nvcuda;

#define DIM 2048
#define NH 32
#define HD 64
#define NB 2
#define NQ 4096
#define NKV 512

// -------- device scratch (allocation-free rule) --------
__device__ __half h_x [(size_t)NB * NQ  * DIM];
__device__ __half h_cx[(size_t)NB * NKV * DIM];
__device__ __half h_wq[(size_t)DIM * DIM];
__device__ __half h_wk[(size_t)DIM * DIM];        // gathered rows h*128+2d
__device__ __half h_wv[(size_t)DIM * DIM];        // gathered rows h*128+2d+1
__device__ __half g_q[(size_t)NB * NH * NQ  * HD];
__device__ __half g_k[(size_t)NB * NH * NKV * HD];
__device__ __half g_v[(size_t)NB * NH * HD * NKV]; // (b,h,d,m) transposed

// ===========================================================================
// Conversion prepass
// ===========================================================================
__global__ __launch_bounds__(256) void conv_f2h(const float* __restrict__ src,
                                                __half* __restrict__ dst)
{
    size_t i = ((size_t)blockIdx.x * 256 + threadIdx.x) * 4;
    float4 v = *(const float4*)&src[i];
    __half o[4] = { __float2half_rn(v.x), __float2half_rn(v.y),
                    __float2half_rn(v.z), __float2half_rn(v.w) };
    *(uint2*)&dst[i] = *(uint2*)o;
}

__global__ __launch_bounds__(256) void conv_wkv(const float* __restrict__ Wk,
                                                const float* __restrict__ Wv)
{
    int j = blockIdx.y;
    int c = (blockIdx.x * 256 + threadIdx.x) * 4;
    int h = j >> 6, d = j & 63;
    int g = h * 128 + 2 * d;
    const float* srcK = (g < DIM) ? (Wk + (size_t)g * DIM) : (Wv + (size_t)(g - DIM) * DIM);
    const float* srcV = (g + 1 < DIM) ? (Wk + (size_t)(g + 1) * DIM)
                                      : (Wv + (size_t)(g + 1 - DIM) * DIM);
    float4 vk = *(const float4*)&srcK[c];
    float4 vv = *(const float4*)&srcV[c];
    __half ok[4] = { __float2half_rn(vk.x), __float2half_rn(vk.y),
                     __float2half_rn(vk.z), __float2half_rn(vk.w) };
    __half ov[4] = { __float2half_rn(vv.x), __float2half_rn(vv.y),
                     __float2half_rn(vv.z), __float2half_rn(vv.w) };
    *(uint2*)&h_wk[(size_t)j * DIM + c] = *(uint2*)ok;
    *(uint2*)&h_wv[(size_t)j * DIM + c] = *(uint2*)ov;
}

// common cp.async macros
#define CP16(d, s) asm volatile("cp.async.cg.shared.global [%0], [%1], 16;" :: "r"(d), "l"(s))
#define CP_COMMIT() asm volatile("cp.async.commit_group;" ::: "memory")
#define CP_WAIT(n)  asm volatile("cp.async.wait_group %0;" :: "n"(n) : "memory")

#define KC 32
#define KCP2 40          // halves per smem row (80 B)
#define ROWB 80
#define CLD2 136
#define NCHUNK (DIM / KC)

// ===========================================================================
// Q projection: 256x128 CTA tile, 8 warps in 4x2, 64x64 warp tiles.
// cp.async 2-stage. RMSNorm*0.125 epilogue -> g_q (b,h,n,d).
// ===========================================================================
#define QBM 256
#define QBN 128
#define QABYTES (QBM * ROWB)          // 20480
#define QBBYTES (QBN * ROWB)          // 10240
#define QSTAGE (QABYTES + QBBYTES)    // 30720
#define QSMEM 69632                   // max(2*QSTAGE=61440, 256*136*2=69632)

__global__ __launch_bounds__(256, 1) void proj_q(
    const __half* __restrict__ A, const __half* __restrict__ Bm)
{
    extern __shared__ char smraw[];
    uint32_t sbase;
    asm("{ .reg .u64 t; cvta.to.shared.u64 t, %1; cvt.u32.u64 %0, t; }"
        : "=r"(sbase) : "l"(smraw));

    const int m0 = blockIdx.x * QBM;
    const int n0 = blockIdx.y * QBN;
    const int t = threadIdx.x;
    const int warp = t >> 5;
    const int wr = warp & 3;     // 64-row group
    const int wc = warp >> 2;    // 64-col group

    wmma::fragment<wmma::accumulator, 16, 16, 16, float> c[4][4];
#pragma unroll
    for (int i = 0; i < 4; i++)
#pragma unroll
        for (int j = 0; j < 4; j++) wmma::fill_fragment(c[i][j], 0.0f);

    // cp.async issuance: 1024 A-chunks + 512 B-chunks of 16B per stage, 6/thread
    const __half* gsrc[6];
    uint32_t doff[6];
#pragma unroll
    for (int j = 0; j < 6; j++) {
        int cidx = t + j * 256;
        if (cidx < 1024) {
            int r = cidx >> 2, sl = cidx & 3;
            gsrc[j] = A + (size_t)(m0 + r) * DIM + sl * 8;
            doff[j] = r * ROWB + sl * 16;
        } else {
            int r = (cidx - 1024) >> 2, sl = cidx & 3;
            gsrc[j] = Bm + (size_t)(n0 + r) * DIM + sl * 8;
            doff[j] = QABYTES + r * ROWB + sl * 16;
        }
    }

#define QISSUE(s, k0) do { \
        _Pragma("unroll") \
        for (int j = 0; j < 6; j++) \
            CP16(sbase + (s) * QSTAGE + doff[j], gsrc[j] + (k0)); \
        CP_COMMIT(); \
    } while (0)

    QISSUE(0, 0);

    for (int i = 0; i < NCHUNK; i++) {
        const int p = i & 1;
        if (i + 1 < NCHUNK) { QISSUE(p ^ 1, (i + 1) * KC); CP_WAIT(1); }
        else                { CP_WAIT(0); }
        __syncthreads();

        const __half* As = (const __half*)(smraw + p * QSTAGE);
        const __half* Bs = (const __half*)(smraw + p * QSTAGE + QABYTES);
#pragma unroll
        for (int ks = 0; ks < KC; ks += 16) {
            wmma::fragment<wmma::matrix_a, 16, 16, 16, __half, wmma::row_major> a[4];
#pragma unroll
            for (int ii = 0; ii < 4; ii++)
                wmma::load_matrix_sync(a[ii], &As[(wr * 64 + ii * 16) * KCP2 + ks], KCP2);
#pragma unroll
            for (int nt = 0; nt < 4; nt++) {
                wmma::fragment<wmma::matrix_b, 16, 16, 16, __half, wmma::col_major> b;
                wmma::load_matrix_sync(b, &Bs[(wc * 64 + nt * 16) * KCP2 + ks], KCP2);
#pragma unroll
                for (int ii = 0; ii < 4; ii++)
                    wmma::mma_sync(c[ii][nt], a[ii], b, c[ii][nt]);
            }
        }
        __syncthreads();
    }

    // epilogue: stage as half, per-head RMSNorm * 0.125, write g_q
    __half* Cs = (__half*)smraw;   // QBM x CLD2
#pragma unroll
    for (int ii = 0; ii < 4; ii++)
#pragma unroll
        for (int nt = 0; nt < 4; nt++) {
            wmma::fragment<wmma::accumulator, 16, 16, 16, __half> ch;
#pragma unroll
            for (int e = 0; e < ch.num_elements; e++)
                ch.x[e] = __float2half_rn(c[ii][nt].x[e]);
            wmma::store_matrix_sync(&Cs[(wr * 64 + ii * 16) * CLD2 + wc * 64 + nt * 16],
                                    ch, CLD2, wmma::mem_row_major);
        }
    __syncthreads();

    __shared__ float sscale[QBM * 2];
    {
        int row = t;   // 0..255, both head groups
#pragma unroll
        for (int g = 0; g < 2; g++) {
            const __half* cr = &Cs[row * CLD2 + g * 64];
            float ss = 0.0f;
#pragma unroll
            for (int d = 0; d < 64; d++) { float v = __half2float(cr[d]); ss += v * v; }
            sscale[row * 2 + g] = rsqrtf(ss * (1.0f / 64.0f) + 1e-6f) * 0.125f;
        }
    }
    __syncthreads();

#pragma unroll
    for (int it = 0; it < 32; it++) {
        int f = t + it * 256;        // 8192 chunks of 4 halves
        int row = f >> 5;
        int j = (f & 31) << 2;
        int g = j >> 6;
        int d = j & 63;
        int gi = m0 + row;
        int bb = gi >> 12, n = gi & 4095;
        int h = (n0 >> 6) + g;
        float sc = sscale[row * 2 + g];
        const __half* cr = &Cs[row * CLD2 + j];
        __half o[4];
#pragma unroll
        for (int u = 0; u < 4; u++)
            o[u] = __float2half_rn(__half2float(cr[u]) * sc);
        *(uint2*)&g_q[(((size_t)bb * NH + h) * NQ + n) * HD + d] = *(uint2*)o;
    }
}

// ===========================================================================
// KV projection (R6 version, 128x128): MODE 1 k (norm), MODE 2 v (transposed)
// ===========================================================================
#define BM 128
#define ABYTES (BM * ROWB)            // 10240
#define STAGE (2 * ABYTES)            // 20480
#define PROJ_SMEM (2 * STAGE)         // 40960

template <int MODE>
__global__ __launch_bounds__(256, 2) void proj_fp16(
    const __half* __restrict__ A, const __half* __restrict__ Bm)
{
    extern __shared__ char smraw[];
    uint32_t sbase;
    asm("{ .reg .u64 t; cvta.to.shared.u64 t, %1; cvt.u32.u64 %0, t; }"
        : "=r"(sbase) : "l"(smraw));
    constexpr int NSEQ = NKV;

    const int m0 = blockIdx.x * BM;
    const int n0 = blockIdx.y * BM;
    const int t = threadIdx.x;
    const int warp = t >> 5;
    const int wr = warp & 3;
    const int wc = warp >> 2;

    wmma::fragment<wmma::accumulator, 16, 16, 16, float> c[2][4];
#pragma unroll
    for (int i = 0; i < 2; i++)
#pragma unroll
        for (int j = 0; j < 4; j++) wmma::fill_fragment(c[i][j], 0.0f);

    const int r0 = t >> 2, c0 = t & 3;
    const int r1 = (t + 256) >> 2, c1 = (t + 256) & 3;
    const __half* arow0 = A + (size_t)(m0 + r0) * DIM + c0 * 8;
    const __half* arow1 = A + (size_t)(m0 + r1) * DIM + c1 * 8;
    const __half* brow0 = Bm + (size_t)(n0 + r0) * DIM + c0 * 8;
    const __half* brow1 = Bm + (size_t)(n0 + r1) * DIM + c1 * 8;
    const uint32_t da0 = sbase + r0 * ROWB + c0 * 16;
    const uint32_t da1 = sbase + r1 * ROWB + c1 * 16;

#define ISSUE(s, k0) do { \
        CP16(da0 + (s) * STAGE, arow0 + (k0)); \
        CP16(da1 + (s) * STAGE, arow1 + (k0)); \
        CP16(da0 + (s) * STAGE + ABYTES, brow0 + (k0)); \
        CP16(da1 + (s) * STAGE + ABYTES, brow1 + (k0)); \
        CP_COMMIT(); \
    } while (0)

    ISSUE(0, 0);

    for (int i = 0; i < NCHUNK; i++) {
        const int p = i & 1;
        if (i + 1 < NCHUNK) { ISSUE(p ^ 1, (i + 1) * KC); CP_WAIT(1); }
        else                { CP_WAIT(0); }
        __syncthreads();

        const __half* As = (const __half*)(smraw + p * STAGE);
        const __half* Bs = (const __half*)(smraw + p * STAGE + ABYTES);
#pragma unroll
        for (int ks = 0; ks < KC; ks += 16) {
            wmma::fragment<wmma::matrix_a, 16, 16, 16, __half, wmma::row_major> a0, a1;
            wmma::load_matrix_sync(a0, &As[(wr * 32) * KCP2 + ks], KCP2);
            wmma::load_matrix_sync(a1, &As[(wr * 32 + 16) * KCP2 + ks], KCP2);
#pragma unroll
            for (int nt = 0; nt < 4; nt++) {
                wmma::fragment<wmma::matrix_b, 16, 16, 16, __half, wmma::col_major> b;
                wmma::load_matrix_sync(b, &Bs[(wc * 64 + nt * 16) * KCP2 + ks], KCP2);
                wmma::mma_sync(c[0][nt], a0, b, c[0][nt]);
                wmma::mma_sync(c[1][nt], a1, b, c[1][nt]);
            }
        }
        __syncthreads();
    }

    __half* Cs = (__half*)smraw;
#pragma unroll
    for (int i = 0; i < 2; i++)
#pragma unroll
        for (int nt = 0; nt < 4; nt++) {
            wmma::fragment<wmma::accumulator, 16, 16, 16, __half> ch;
#pragma unroll
            for (int e = 0; e < ch.num_elements; e++)
                ch.x[e] = __float2half_rn(c[i][nt].x[e]);
            wmma::store_matrix_sync(&Cs[(wr * 32 + i * 16) * CLD2 + wc * 64 + nt * 16],
                                    ch, CLD2, wmma::mem_row_major);
        }
    __syncthreads();

    __shared__ float sscale[BM * 2];
    {
        int row = t >> 1, g = t & 1;
        float s = 1.0f;
        if (MODE != 2) {
            const __half* cr = &Cs[row * CLD2 + g * 64];
            float ss = 0.0f;
#pragma unroll
            for (int d = 0; d < 64; d++) { float v = __half2float(cr[d]); ss += v * v; }
            s = rsqrtf(ss * (1.0f / 64.0f) + 1e-6f);
        }
        sscale[row * 2 + g] = s;
    }
    __syncthreads();

#pragma unroll
    for (int it = 0; it < 16; it++) {
        int f = t + it * 256;
        int row = f >> 5;
        int j = (f & 31) << 2;
        int g = j >> 6;
        int d = j & 63;
        int gi = m0 + row;
        int bb = gi / NSEQ, n = gi % NSEQ;
        int h = (n0 >> 6) + g;
        float sc = sscale[row * 2 + g];
        const __half* cr = &Cs[row * CLD2 + j];
        __half o[4];
#pragma unroll
        for (int u = 0; u < 4; u++)
            o[u] = __float2half_rn(__half2float(cr[u]) * sc);
        if (MODE == 2) {
#pragma unroll
            for (int u = 0; u < 4; u++)
                g_v[(((size_t)bb * NH + h) * HD + d + u) * NKV + n] = o[u];
        } else {
            *(uint2*)&g_k[(((size_t)bb * NH + h) * NSEQ + n) * HD + d] = *(uint2*)o;
        }
    }
}

// ===========================================================================
// FlashAttention-2 style fused attention (unchanged, known good)
// ===========================================================================
#define ATQ 64
#define KVT 64
#define TLD 72

__device__ __forceinline__ void mma16816(float* c, const uint32_t* a,
                                         uint32_t b0, uint32_t b1)
{
    asm volatile(
        "mma.sync.aligned.m16n8k16.row.col.f32.f16.f16.f32 "
        "{%0,%1,%2,%3}, {%4,%5,%6,%7}, {%8,%9}, {%0,%1,%2,%3};"
        : "+f"(c[0]), "+f"(c[1]), "+f"(c[2]), "+f"(c[3])
        : "r"(a[0]), "r"(a[1]), "r"(a[2]), "r"(a[3]), "r"(b0), "r"(b1));
}

__global__ __launch_bounds__(128) void attn_fa(float* __restrict__ out)
{
    __shared__ __half Ks[KVT * TLD];
    __shared__ __half Vs[HD * TLD];

    const int t = threadIdx.x;
    const int warp = t >> 5, lane = t & 31;
    const int group = lane >> 2, tig = lane & 3;
    const int q0 = blockIdx.x * ATQ;
    const int h = blockIdx.y, b = blockIdx.z;

    const __half* qbase = g_q + (((size_t)b * NH + h) * NQ + q0 + warp * 16) * HD;
    const __half* kbase = g_k + ((size_t)b * NH + h) * NKV * HD;
    const __half* vtbase = g_v + ((size_t)b * NH + h) * HD * NKV;

    uint32_t qa[4][4];
    {
        const __half* qrA = qbase + group * HD;
        const __half* qrB = qbase + (group + 8) * HD;
#pragma unroll
        for (int i = 0; i < 4; i++) {
            qa[i][0] = *(const uint32_t*)&qrA[i * 16 + tig * 2];
            qa[i][1] = *(const uint32_t*)&qrB[i * 16 + tig * 2];
            qa[i][2] = *(const uint32_t*)&qrA[i * 16 + 8 + tig * 2];
            qa[i][3] = *(const uint32_t*)&qrB[i * 16 + 8 + tig * 2];
        }
    }

    float o[8][4];
#pragma unroll
    for (int j = 0; j < 8; j++)
        o[j][0] = o[j][1] = o[j][2] = o[j][3] = 0.0f;
    float mA = -1e30f, mB = -1e30f, lA = 0.0f, lB = 0.0f;

    for (int kt = 0; kt < 8; kt++) {
        __syncthreads();
#pragma unroll
        for (int it = 0; it < 4; it++) {
            int f = t + it * 128;
            int r = f >> 3, c8 = (f & 7) * 8;
            *(uint4*)&Ks[r * TLD + c8] = *(const uint4*)&kbase[(kt * 64 + r) * HD + c8];
            *(uint4*)&Vs[r * TLD + c8] = *(const uint4*)&vtbase[(size_t)r * NKV + kt * 64 + c8];
        }
        __syncthreads();

        float s[8][4];
#pragma unroll
        for (int j = 0; j < 8; j++) {
            s[j][0] = s[j][1] = s[j][2] = s[j][3] = 0.0f;
            const __half* kr = &Ks[(j * 8 + group) * TLD + tig * 2];
#pragma unroll
            for (int i = 0; i < 4; i++) {
                uint32_t b0 = *(const uint32_t*)&kr[i * 16];
                uint32_t b1 = *(const uint32_t*)&kr[i * 16 + 8];
                mma16816(s[j], qa[i], b0, b1);
            }
        }

        float tAm = -1e30f, tBm = -1e30f;
#pragma unroll
        for (int j = 0; j < 8; j++) {
            tAm = fmaxf(tAm, fmaxf(s[j][0], s[j][1]));
            tBm = fmaxf(tBm, fmaxf(s[j][2], s[j][3]));
        }
        tAm = fmaxf(tAm, __shfl_xor_sync(0xffffffffu, tAm, 1));
        tAm = fmaxf(tAm, __shfl_xor_sync(0xffffffffu, tAm, 2));
        tBm = fmaxf(tBm, __shfl_xor_sync(0xffffffffu, tBm, 1));
        tBm = fmaxf(tBm, __shfl_xor_sync(0xffffffffu, tBm, 2));
        float nmA = fmaxf(mA, tAm), nmB = fmaxf(mB, tBm);
        float cA = __expf(mA - nmA), cB = __expf(mB - nmB);
        mA = nmA; mB = nmB;
        lA *= cA; lB *= cB;
#pragma unroll
        for (int j = 0; j < 8; j++) {
            o[j][0] *= cA; o[j][1] *= cA;
            o[j][2] *= cB; o[j][3] *= cB;
        }

        uint32_t ph[8][2];
        float sumA = 0.0f, sumB = 0.0f;
#pragma unroll
        for (int j = 0; j < 8; j++) {
            float e0 = __expf(s[j][0] - nmA);
            float e1 = __expf(s[j][1] - nmA);
            float e2 = __expf(s[j][2] - nmB);
            float e3 = __expf(s[j][3] - nmB);
            sumA += e0 + e1; sumB += e2 + e3;
            __half2 p01 = __floats2half2_rn(e0, e1);
            __half2 p23 = __floats2half2_rn(e2, e3);
            ph[j][0] = *(uint32_t*)&p01;
            ph[j][1] = *(uint32_t*)&p23;
        }
        lA += sumA; lB += sumB;

#pragma unroll
        for (int i2 = 0; i2 < 4; i2++) {
            uint32_t pa[4] = { ph[2 * i2][0], ph[2 * i2][1],
                               ph[2 * i2 + 1][0], ph[2 * i2 + 1][1] };
#pragma unroll
            for (int j3 = 0; j3 < 8; j3++) {
                const __half* vr = &Vs[(j3 * 8 + group) * TLD + tig * 2];
                uint32_t b0 = *(const uint32_t*)&vr[i2 * 16];
                uint32_t b1 = *(const uint32_t*)&vr[i2 * 16 + 8];
                mma16816(o[j3], pa, b0, b1);
            }
        }
    }

    lA += __shfl_xor_sync(0xffffffffu, lA, 1);
    lA += __shfl_xor_sync(0xffffffffu, lA, 2);
    lB += __shfl_xor_sync(0xffffffffu, lB, 1);
    lB += __shfl_xor_sync(0xffffffffu, lB, 2);
    float rA = 1.0f / lA, rB = 1.0f / lB;

    float* obase = out + ((size_t)b * NQ + q0 + warp * 16) * DIM + h * HD;
#pragma unroll
    for (int j3 = 0; j3 < 8; j3++) {
        float2 vA = { o[j3][0] * rA, o[j3][1] * rA };
        float2 vB = { o[j3][2] * rB, o[j3][3] * rB };
        *(float2*)&obase[(size_t)group * DIM + j3 * 8 + tig * 2] = vA;
        *(float2*)&obase[(size_t)(group + 8) * DIM + j3 * 8 + tig * 2] = vB;
    }
}

// ---------------------------------------------------------------------------
extern "C" void kernel_launch(void* const* d_in, const int* in_sizes, int n_in,
                              void* d_out, int out_size)
{
    const float* x  = (const float*)d_in[0];
    const float* cx = (const float*)d_in[1];
    const float* Wq = (const float*)d_in[2];
    const float* Wk = (const float*)d_in[3];
    const float* Wv = (const float*)d_in[4];
    float* out = (float*)d_out;

    __half *dx, *dcx, *dwq, *dwk, *dwv;
    cudaGetSymbolAddress((void**)&dx,  h_x);
    cudaGetSymbolAddress((void**)&dcx, h_cx);
    cudaGetSymbolAddress((void**)&dwq, h_wq);
    cudaGetSymbolAddress((void**)&dwk, h_wk);
    cudaGetSymbolAddress((void**)&dwv, h_wv);

    // fp32 -> fp16 conversion prepass
    conv_f2h<<<(NB * NQ * DIM) / 1024, 256>>>(x, dx);
    conv_f2h<<<(NB * NKV * DIM) / 1024, 256>>>(cx, dcx);
    conv_f2h<<<(DIM * DIM) / 1024, 256>>>(Wq, dwq);
    conv_wkv<<<dim3(2, DIM), 256>>>(Wk, Wv);

    cudaFuncSetAttribute((const void*)proj_q,
                         cudaFuncAttributeMaxDynamicSharedMemorySize, QSMEM);
    cudaFuncSetAttribute((const void*)proj_fp16<1>,
                         cudaFuncAttributeMaxDynamicSharedMemorySize, PROJ_SMEM);
    cudaFuncSetAttribute((const void*)proj_fp16<2>,
                         cudaFuncAttributeMaxDynamicSharedMemorySize, PROJ_SMEM);

    // q projection: 8192 rows -> 32 x 16 tiles of 256x128
    proj_q<<<dim3(32, 16), 256, QSMEM>>>(dx, dwq);
    // k / v projections
    proj_fp16<1><<<dim3(8, 16), 256, PROJ_SMEM>>>(dcx, dwk);
    proj_fp16<2><<<dim3(8, 16), 256, PROJ_SMEM>>>(dcx, dwv);
    // fused attention
    attn_fa<<<dim3(NQ / ATQ, NH, NB), 128>>>(out);
}

// round 8
// speedup vs baseline: 1.0990x; 1.0990x over previous
#include <cuda_runtime.h>
#include <cuda_fp16.h>
#include <cstdint>
#include <mma.h>
using namespace nvcuda;

#define DIM 2048
#define NH 32
#define HD 64
#define NB 2
#define NQ 4096
#define NKV 512

// -------- device scratch (allocation-free rule) --------
__device__ __half h_x [(size_t)NB * NQ  * DIM];
__device__ __half h_cx[(size_t)NB * NKV * DIM];
__device__ __half h_wq[(size_t)DIM * DIM];
__device__ __half h_wk[(size_t)DIM * DIM];        // gathered rows h*128+2d
__device__ __half h_wv[(size_t)DIM * DIM];        // gathered rows h*128+2d+1
__device__ __half g_q[(size_t)NB * NH * NQ  * HD];
__device__ __half g_k[(size_t)NB * NH * NKV * HD];
__device__ __half g_v[(size_t)NB * NH * HD * NKV]; // (b,h,d,m) transposed

// ===========================================================================
// Conversion prepass
// ===========================================================================
__global__ __launch_bounds__(256) void conv_f2h(const float* __restrict__ src,
                                                __half* __restrict__ dst)
{
    size_t i = ((size_t)blockIdx.x * 256 + threadIdx.x) * 4;
    float4 v = *(const float4*)&src[i];
    __half o[4] = { __float2half_rn(v.x), __float2half_rn(v.y),
                    __float2half_rn(v.z), __float2half_rn(v.w) };
    *(uint2*)&dst[i] = *(uint2*)o;
}

__global__ __launch_bounds__(256) void conv_wkv(const float* __restrict__ Wk,
                                                const float* __restrict__ Wv)
{
    int j = blockIdx.y;
    int c = (blockIdx.x * 256 + threadIdx.x) * 4;
    int h = j >> 6, d = j & 63;
    int g = h * 128 + 2 * d;
    const float* srcK = (g < DIM) ? (Wk + (size_t)g * DIM) : (Wv + (size_t)(g - DIM) * DIM);
    const float* srcV = (g + 1 < DIM) ? (Wk + (size_t)(g + 1) * DIM)
                                      : (Wv + (size_t)(g + 1 - DIM) * DIM);
    float4 vk = *(const float4*)&srcK[c];
    float4 vv = *(const float4*)&srcV[c];
    __half ok[4] = { __float2half_rn(vk.x), __float2half_rn(vk.y),
                     __float2half_rn(vk.z), __float2half_rn(vk.w) };
    __half ov[4] = { __float2half_rn(vv.x), __float2half_rn(vv.y),
                     __float2half_rn(vv.z), __float2half_rn(vv.w) };
    *(uint2*)&h_wk[(size_t)j * DIM + c] = *(uint2*)ok;
    *(uint2*)&h_wv[(size_t)j * DIM + c] = *(uint2*)ov;
}

// common cp.async macros
#define CP16(d, s) asm volatile("cp.async.cg.shared.global [%0], [%1], 16;" :: "r"(d), "l"(s))
#define CP_COMMIT() asm volatile("cp.async.commit_group;" ::: "memory")
#define CP_WAIT(n)  asm volatile("cp.async.wait_group %0;" :: "n"(n) : "memory")

#define KC 32
#define KCP2 40          // halves per smem row (80 B)
#define ROWB 80
#define CLD2 136
#define NCHUNK (DIM / KC)

#define BM 128
#define ABYTES (BM * ROWB)            // 10240
#define STAGE (2 * ABYTES)            // 20480

// ===========================================================================
// Projection GEMM 128x128 (R6 config, 2 CTAs/SM).
// QSTAGES=3 for q (MODE 0), 2 for kv. MODE 0: q (norm*0.125)
// MODE 1: k (norm). MODE 2: v (no norm, transposed output).
// ===========================================================================
template <int MODE, int NSTG>
__global__ __launch_bounds__(256, 2) void proj_fp16(
    const __half* __restrict__ A, const __half* __restrict__ Bm)
{
    extern __shared__ char smraw[];
    uint32_t sbase;
    asm("{ .reg .u64 t; cvta.to.shared.u64 t, %1; cvt.u32.u64 %0, t; }"
        : "=r"(sbase) : "l"(smraw));
    constexpr int NSEQ = (MODE == 0) ? NQ : NKV;

    const int m0 = blockIdx.x * BM;
    const int n0 = blockIdx.y * BM;
    const int t = threadIdx.x;
    const int warp = t >> 5;
    const int wr = warp & 3;
    const int wc = warp >> 2;

    wmma::fragment<wmma::accumulator, 16, 16, 16, float> c[2][4];
#pragma unroll
    for (int i = 0; i < 2; i++)
#pragma unroll
        for (int j = 0; j < 4; j++) wmma::fill_fragment(c[i][j], 0.0f);

    const int r0 = t >> 2, c0 = t & 3;
    const int r1 = (t + 256) >> 2, c1 = (t + 256) & 3;
    const __half* arow0 = A + (size_t)(m0 + r0) * DIM + c0 * 8;
    const __half* arow1 = A + (size_t)(m0 + r1) * DIM + c1 * 8;
    const __half* brow0 = Bm + (size_t)(n0 + r0) * DIM + c0 * 8;
    const __half* brow1 = Bm + (size_t)(n0 + r1) * DIM + c1 * 8;
    const uint32_t da0 = sbase + r0 * ROWB + c0 * 16;
    const uint32_t da1 = sbase + r1 * ROWB + c1 * 16;

#define ISSUE(s, k0) do { \
        CP16(da0 + (s) * STAGE, arow0 + (k0)); \
        CP16(da1 + (s) * STAGE, arow1 + (k0)); \
        CP16(da0 + (s) * STAGE + ABYTES, brow0 + (k0)); \
        CP16(da1 + (s) * STAGE + ABYTES, brow1 + (k0)); \
        CP_COMMIT(); \
    } while (0)

    ISSUE(0, 0);
    if (NSTG == 3) ISSUE(1, KC);

    for (int i = 0; i < NCHUNK; i++) {
        const int p = (NSTG == 3) ? (i % 3) : (i & 1);
        if (NSTG == 3) {
            if (i + 2 < NCHUNK)      { ISSUE((i + 2) % 3, (i + 2) * KC); CP_WAIT(2); }
            else if (i + 1 < NCHUNK) { CP_WAIT(1); }
            else                     { CP_WAIT(0); }
        } else {
            if (i + 1 < NCHUNK) { ISSUE(p ^ 1, (i + 1) * KC); CP_WAIT(1); }
            else                { CP_WAIT(0); }
        }
        __syncthreads();

        const __half* As = (const __half*)(smraw + p * STAGE);
        const __half* Bs = (const __half*)(smraw + p * STAGE + ABYTES);
#pragma unroll
        for (int ks = 0; ks < KC; ks += 16) {
            wmma::fragment<wmma::matrix_a, 16, 16, 16, __half, wmma::row_major> a0, a1;
            wmma::load_matrix_sync(a0, &As[(wr * 32) * KCP2 + ks], KCP2);
            wmma::load_matrix_sync(a1, &As[(wr * 32 + 16) * KCP2 + ks], KCP2);
#pragma unroll
            for (int nt = 0; nt < 4; nt++) {
                wmma::fragment<wmma::matrix_b, 16, 16, 16, __half, wmma::col_major> b;
                wmma::load_matrix_sync(b, &Bs[(wc * 64 + nt * 16) * KCP2 + ks], KCP2);
                wmma::mma_sync(c[0][nt], a0, b, c[0][nt]);
                wmma::mma_sync(c[1][nt], a1, b, c[1][nt]);
            }
        }
        __syncthreads();
    }

    // epilogue: stage C as half, per-head RMSNorm, write scratch
    __half* Cs = (__half*)smraw;
#pragma unroll
    for (int i = 0; i < 2; i++)
#pragma unroll
        for (int nt = 0; nt < 4; nt++) {
            wmma::fragment<wmma::accumulator, 16, 16, 16, __half> ch;
#pragma unroll
            for (int e = 0; e < ch.num_elements; e++)
                ch.x[e] = __float2half_rn(c[i][nt].x[e]);
            wmma::store_matrix_sync(&Cs[(wr * 32 + i * 16) * CLD2 + wc * 64 + nt * 16],
                                    ch, CLD2, wmma::mem_row_major);
        }
    __syncthreads();

    __shared__ float sscale[BM * 2];
    {
        int row = t >> 1, g = t & 1;
        float s = 1.0f;
        if (MODE != 2) {
            const __half* cr = &Cs[row * CLD2 + g * 64];
            float ss = 0.0f;
#pragma unroll
            for (int d = 0; d < 64; d++) { float v = __half2float(cr[d]); ss += v * v; }
            s = rsqrtf(ss * (1.0f / 64.0f) + 1e-6f);
            if (MODE == 0) s *= 0.125f;
        }
        sscale[row * 2 + g] = s;
    }
    __syncthreads();

#pragma unroll
    for (int it = 0; it < 16; it++) {
        int f = t + it * 256;
        int row = f >> 5;
        int j = (f & 31) << 2;
        int g = j >> 6;
        int d = j & 63;
        int gi = m0 + row;
        int bb = gi / NSEQ, n = gi % NSEQ;
        int h = (n0 >> 6) + g;
        float sc = sscale[row * 2 + g];
        const __half* cr = &Cs[row * CLD2 + j];
        __half o[4];
#pragma unroll
        for (int u = 0; u < 4; u++)
            o[u] = __float2half_rn(__half2float(cr[u]) * sc);
        if (MODE == 2) {
#pragma unroll
            for (int u = 0; u < 4; u++)
                g_v[(((size_t)bb * NH + h) * HD + d + u) * NKV + n] = o[u];
        } else {
            __half* dst = (MODE == 0) ? g_q : g_k;
            *(uint2*)&dst[(((size_t)bb * NH + h) * NSEQ + n) * HD + d] = *(uint2*)o;
        }
    }
}

#define PROJ_SMEM_Q (3 * STAGE)   // 61440
#define PROJ_SMEM_KV (2 * STAGE)  // 40960

// ===========================================================================
// FlashAttention-2 attention with cp.async double-buffered K/V tiles.
// ===========================================================================
#define ATQ 64
#define KVT 64
#define TLD 72

__device__ __forceinline__ void mma16816(float* c, const uint32_t* a,
                                         uint32_t b0, uint32_t b1)
{
    asm volatile(
        "mma.sync.aligned.m16n8k16.row.col.f32.f16.f16.f32 "
        "{%0,%1,%2,%3}, {%4,%5,%6,%7}, {%8,%9}, {%0,%1,%2,%3};"
        : "+f"(c[0]), "+f"(c[1]), "+f"(c[2]), "+f"(c[3])
        : "r"(a[0]), "r"(a[1]), "r"(a[2]), "r"(a[3]), "r"(b0), "r"(b1));
}

__global__ __launch_bounds__(128) void attn_fa(float* __restrict__ out)
{
    __shared__ __half Ks[2][KVT * TLD];
    __shared__ __half Vs[2][HD * TLD];

    const int t = threadIdx.x;
    const int warp = t >> 5, lane = t & 31;
    const int group = lane >> 2, tig = lane & 3;
    const int q0 = blockIdx.x * ATQ;
    const int h = blockIdx.y, b = blockIdx.z;

    const __half* qbase = g_q + (((size_t)b * NH + h) * NQ + q0 + warp * 16) * HD;
    const __half* kbase = g_k + ((size_t)b * NH + h) * NKV * HD;
    const __half* vtbase = g_v + ((size_t)b * NH + h) * HD * NKV;

    uint32_t ksb, vsb;
    asm("{ .reg .u64 u; cvta.to.shared.u64 u, %1; cvt.u32.u64 %0, u; }" : "=r"(ksb) : "l"(&Ks[0][0]));
    asm("{ .reg .u64 u; cvta.to.shared.u64 u, %1; cvt.u32.u64 %0, u; }" : "=r"(vsb) : "l"(&Vs[0][0]));

    // per-thread cp.async chunk map: 512 16B chunks per matrix, 4 per thread
    int rr[4], cc[4];
#pragma unroll
    for (int it = 0; it < 4; it++) {
        int f = t + it * 128;
        rr[it] = f >> 3;
        cc[it] = (f & 7) * 8;
    }

#define AISSUE(kt, p) do { \
        _Pragma("unroll") \
        for (int it = 0; it < 4; it++) { \
            CP16(ksb + ((p) * KVT * TLD + rr[it] * TLD + cc[it]) * 2, \
                 &kbase[((kt) * 64 + rr[it]) * HD + cc[it]]); \
            CP16(vsb + ((p) * HD * TLD + rr[it] * TLD + cc[it]) * 2, \
                 &vtbase[(size_t)rr[it] * NKV + (kt) * 64 + cc[it]]); \
        } \
        CP_COMMIT(); \
    } while (0)

    uint32_t qa[4][4];
    {
        const __half* qrA = qbase + group * HD;
        const __half* qrB = qbase + (group + 8) * HD;
#pragma unroll
        for (int i = 0; i < 4; i++) {
            qa[i][0] = *(const uint32_t*)&qrA[i * 16 + tig * 2];
            qa[i][1] = *(const uint32_t*)&qrB[i * 16 + tig * 2];
            qa[i][2] = *(const uint32_t*)&qrA[i * 16 + 8 + tig * 2];
            qa[i][3] = *(const uint32_t*)&qrB[i * 16 + 8 + tig * 2];
        }
    }

    AISSUE(0, 0);

    float o[8][4];
#pragma unroll
    for (int j = 0; j < 8; j++)
        o[j][0] = o[j][1] = o[j][2] = o[j][3] = 0.0f;
    float mA = -1e30f, mB = -1e30f, lA = 0.0f, lB = 0.0f;

    for (int kt = 0; kt < 8; kt++) {
        const int p = kt & 1;
        if (kt < 7) { AISSUE(kt + 1, p ^ 1); CP_WAIT(1); }
        else        { CP_WAIT(0); }
        __syncthreads();

        float s[8][4];
#pragma unroll
        for (int j = 0; j < 8; j++) {
            s[j][0] = s[j][1] = s[j][2] = s[j][3] = 0.0f;
            const __half* kr = &Ks[p][(j * 8 + group) * TLD + tig * 2];
#pragma unroll
            for (int i = 0; i < 4; i++) {
                uint32_t b0 = *(const uint32_t*)&kr[i * 16];
                uint32_t b1 = *(const uint32_t*)&kr[i * 16 + 8];
                mma16816(s[j], qa[i], b0, b1);
            }
        }

        float tAm = -1e30f, tBm = -1e30f;
#pragma unroll
        for (int j = 0; j < 8; j++) {
            tAm = fmaxf(tAm, fmaxf(s[j][0], s[j][1]));
            tBm = fmaxf(tBm, fmaxf(s[j][2], s[j][3]));
        }
        tAm = fmaxf(tAm, __shfl_xor_sync(0xffffffffu, tAm, 1));
        tAm = fmaxf(tAm, __shfl_xor_sync(0xffffffffu, tAm, 2));
        tBm = fmaxf(tBm, __shfl_xor_sync(0xffffffffu, tBm, 1));
        tBm = fmaxf(tBm, __shfl_xor_sync(0xffffffffu, tBm, 2));
        float nmA = fmaxf(mA, tAm), nmB = fmaxf(mB, tBm);
        float cA = __expf(mA - nmA), cB = __expf(mB - nmB);
        mA = nmA; mB = nmB;
        lA *= cA; lB *= cB;
#pragma unroll
        for (int j = 0; j < 8; j++) {
            o[j][0] *= cA; o[j][1] *= cA;
            o[j][2] *= cB; o[j][3] *= cB;
        }

        uint32_t ph[8][2];
        float sumA = 0.0f, sumB = 0.0f;
#pragma unroll
        for (int j = 0; j < 8; j++) {
            float e0 = __expf(s[j][0] - nmA);
            float e1 = __expf(s[j][1] - nmA);
            float e2 = __expf(s[j][2] - nmB);
            float e3 = __expf(s[j][3] - nmB);
            sumA += e0 + e1; sumB += e2 + e3;
            __half2 p01 = __floats2half2_rn(e0, e1);
            __half2 p23 = __floats2half2_rn(e2, e3);
            ph[j][0] = *(uint32_t*)&p01;
            ph[j][1] = *(uint32_t*)&p23;
        }
        lA += sumA; lB += sumB;

#pragma unroll
        for (int i2 = 0; i2 < 4; i2++) {
            uint32_t pa[4] = { ph[2 * i2][0], ph[2 * i2][1],
                               ph[2 * i2 + 1][0], ph[2 * i2 + 1][1] };
#pragma unroll
            for (int j3 = 0; j3 < 8; j3++) {
                const __half* vr = &Vs[p][(j3 * 8 + group) * TLD + tig * 2];
                uint32_t b0 = *(const uint32_t*)&vr[i2 * 16];
                uint32_t b1 = *(const uint32_t*)&vr[i2 * 16 + 8];
                mma16816(o[j3], pa, b0, b1);
            }
        }
        __syncthreads();
    }

    lA += __shfl_xor_sync(0xffffffffu, lA, 1);
    lA += __shfl_xor_sync(0xffffffffu, lA, 2);
    lB += __shfl_xor_sync(0xffffffffu, lB, 1);
    lB += __shfl_xor_sync(0xffffffffu, lB, 2);
    float rA = 1.0f / lA, rB = 1.0f / lB;

    float* obase = out + ((size_t)b * NQ + q0 + warp * 16) * DIM + h * HD;
#pragma unroll
    for (int j3 = 0; j3 < 8; j3++) {
        float2 vA = { o[j3][0] * rA, o[j3][1] * rA };
        float2 vB = { o[j3][2] * rB, o[j3][3] * rB };
        *(float2*)&obase[(size_t)group * DIM + j3 * 8 + tig * 2] = vA;
        *(float2*)&obase[(size_t)(group + 8) * DIM + j3 * 8 + tig * 2] = vB;
    }
}

// ---------------------------------------------------------------------------
extern "C" void kernel_launch(void* const* d_in, const int* in_sizes, int n_in,
                              void* d_out, int out_size)
{
    const float* x  = (const float*)d_in[0];
    const float* cx = (const float*)d_in[1];
    const float* Wq = (const float*)d_in[2];
    const float* Wk = (const float*)d_in[3];
    const float* Wv = (const float*)d_in[4];
    float* out = (float*)d_out;

    __half *dx, *dcx, *dwq, *dwk, *dwv;
    cudaGetSymbolAddress((void**)&dx,  h_x);
    cudaGetSymbolAddress((void**)&dcx, h_cx);
    cudaGetSymbolAddress((void**)&dwq, h_wq);
    cudaGetSymbolAddress((void**)&dwk, h_wk);
    cudaGetSymbolAddress((void**)&dwv, h_wv);

    // fp32 -> fp16 conversion prepass
    conv_f2h<<<(NB * NQ * DIM) / 1024, 256>>>(x, dx);
    conv_f2h<<<(NB * NKV * DIM) / 1024, 256>>>(cx, dcx);
    conv_f2h<<<(DIM * DIM) / 1024, 256>>>(Wq, dwq);
    conv_wkv<<<dim3(2, DIM), 256>>>(Wk, Wv);

    cudaFuncSetAttribute((const void*)proj_fp16<0, 3>,
                         cudaFuncAttributeMaxDynamicSharedMemorySize, PROJ_SMEM_Q);
    cudaFuncSetAttribute((const void*)proj_fp16<1, 2>,
                         cudaFuncAttributeMaxDynamicSharedMemorySize, PROJ_SMEM_KV);
    cudaFuncSetAttribute((const void*)proj_fp16<2, 2>,
                         cudaFuncAttributeMaxDynamicSharedMemorySize, PROJ_SMEM_KV);

    // projections
    proj_fp16<0, 3><<<dim3(64, 16), 256, PROJ_SMEM_Q>>>(dx, dwq);
    proj_fp16<1, 2><<<dim3(8, 16), 256, PROJ_SMEM_KV>>>(dcx, dwk);
    proj_fp16<2, 2><<<dim3(8, 16), 256, PROJ_SMEM_KV>>>(dcx, dwv);
    // fused attention (cp.async double-buffered)
    attn_fa<<<dim3(NQ / ATQ, NH, NB), 128>>>(out);
}

// round 9
// speedup vs baseline: 1.2143x; 1.1050x over previous
#include <cuda_runtime.h>
#include <cuda_fp16.h>
#include <cstdint>
#include <mma.h>
using namespace nvcuda;

#define DIM 2048
#define NH 32
#define HD 64
#define NB 2
#define NQ 4096
#define NKV 512

// -------- device scratch (allocation-free rule) --------
__device__ __half h_x [(size_t)NB * NQ  * DIM];
__device__ __half h_cx[(size_t)NB * NKV * DIM];
__device__ __half h_wq[(size_t)DIM * DIM];
__device__ __half h_wk[(size_t)DIM * DIM];        // gathered rows h*128+2d
__device__ __half h_wv[(size_t)DIM * DIM];        // gathered rows h*128+2d+1
__device__ __half g_q[(size_t)NB * NH * NQ  * HD];
__device__ __half g_k[(size_t)NB * NH * NKV * HD];
__device__ __half g_v[(size_t)NB * NH * HD * NKV]; // (b,h,d,m) transposed

// ===========================================================================
// Fused conversion prepass — one launch.
// blocks [0,16384): x -> h_x          (4 float4/thr-block chunks)
// [16384,18432): cx -> h_cx
// [18432,22528): Wq -> h_wq
// [22528,26624): gathered Wk/Wv rows -> h_wk/h_wv
// ===========================================================================
#define CONV_BLOCKS 26624

__global__ __launch_bounds__(256) void conv_all(
    const float* __restrict__ x, const float* __restrict__ cx,
    const float* __restrict__ Wq, const float* __restrict__ Wk,
    const float* __restrict__ Wv)
{
    const int bid = blockIdx.x;
    const int t = threadIdx.x;
    if (bid < 22528) {
        const float* src;
        __half* dst;
        size_t i;
        if (bid < 16384)      { src = x;  dst = h_x;  i = ((size_t)bid * 256 + t) * 4; }
        else if (bid < 18432) { src = cx; dst = h_cx; i = ((size_t)(bid - 16384) * 256 + t) * 4; }
        else                  { src = Wq; dst = h_wq; i = ((size_t)(bid - 18432) * 256 + t) * 4; }
        float4 v = *(const float4*)&src[i];
        __half o[4] = { __float2half_rn(v.x), __float2half_rn(v.y),
                        __float2half_rn(v.z), __float2half_rn(v.w) };
        *(uint2*)&dst[i] = *(uint2*)o;
    } else {
        int i = bid - 22528;
        int j = i >> 1;                       // 0..2047 output row
        int c = ((i & 1) * 256 + t) * 4;      // col
        int h = j >> 6, d = j & 63;
        int g = h * 128 + 2 * d;
        const float* srcK = (g < DIM) ? (Wk + (size_t)g * DIM) : (Wv + (size_t)(g - DIM) * DIM);
        const float* srcV = (g + 1 < DIM) ? (Wk + (size_t)(g + 1) * DIM)
                                          : (Wv + (size_t)(g + 1 - DIM) * DIM);
        float4 vk = *(const float4*)&srcK[c];
        float4 vv = *(const float4*)&srcV[c];
        __half ok[4] = { __float2half_rn(vk.x), __float2half_rn(vk.y),
                         __float2half_rn(vk.z), __float2half_rn(vk.w) };
        __half ov[4] = { __float2half_rn(vv.x), __float2half_rn(vv.y),
                         __float2half_rn(vv.z), __float2half_rn(vv.w) };
        *(uint2*)&h_wk[(size_t)j * DIM + c] = *(uint2*)ok;
        *(uint2*)&h_wv[(size_t)j * DIM + c] = *(uint2*)ov;
    }
}

// common cp.async macros
#define CP16(d, s) asm volatile("cp.async.cg.shared.global [%0], [%1], 16;" :: "r"(d), "l"(s))
#define CP_COMMIT() asm volatile("cp.async.commit_group;" ::: "memory")
#define CP_WAIT(n)  asm volatile("cp.async.wait_group %0;" :: "n"(n) : "memory")

#define KC 32
#define KCP2 40          // halves per smem row (80 B)
#define ROWB 80
#define CLD2 136
#define NCHUNK (DIM / KC)

#define BM 128
#define ABYTES (BM * ROWB)            // 10240
#define STAGE (2 * ABYTES)            // 20480
#define PROJ_SMEM (3 * STAGE)         // 61440, 3-stage; 2 CTAs/SM

// ===========================================================================
// Fused projection GEMM — one 1280-CTA launch, identical work per CTA.
// blocks [0,256): kv  (even: k / MODE1, odd: v / MODE2), 8 x 16 tiles
// blocks [256,1280): q (MODE 0), 64 x 16 tiles
// ===========================================================================
__global__ __launch_bounds__(256, 2) void proj_all()
{
    extern __shared__ char smraw[];
    uint32_t sbase;
    asm("{ .reg .u64 t; cvta.to.shared.u64 t, %1; cvt.u32.u64 %0, t; }"
        : "=r"(sbase) : "l"(smraw));

    // decode
    int mode, mt, nt;
    const __half *A, *Bm;
    {
        int bid = blockIdx.x;
        if (bid < 256) {
            int i = bid >> 1;            // 0..127
            mode = 1 + (bid & 1);
            mt = i & 7; nt = i >> 3;
            A = h_cx; Bm = (mode == 1) ? h_wk : h_wv;
        } else {
            int i = bid - 256;
            mode = 0;
            mt = i & 63; nt = i >> 6;
            A = h_x; Bm = h_wq;
        }
    }
    const int m0 = mt * BM;
    const int n0 = nt * BM;
    const int t = threadIdx.x;
    const int warp = t >> 5;
    const int wr = warp & 3;
    const int wc = warp >> 2;

    wmma::fragment<wmma::accumulator, 16, 16, 16, float> c[2][4];
#pragma unroll
    for (int i = 0; i < 2; i++)
#pragma unroll
        for (int j = 0; j < 4; j++) wmma::fill_fragment(c[i][j], 0.0f);

    const int r0 = t >> 2, c0 = t & 3;
    const int r1 = (t + 256) >> 2, c1 = (t + 256) & 3;
    const __half* arow0 = A + (size_t)(m0 + r0) * DIM + c0 * 8;
    const __half* arow1 = A + (size_t)(m0 + r1) * DIM + c1 * 8;
    const __half* brow0 = Bm + (size_t)(n0 + r0) * DIM + c0 * 8;
    const __half* brow1 = Bm + (size_t)(n0 + r1) * DIM + c1 * 8;
    const uint32_t da0 = sbase + r0 * ROWB + c0 * 16;
    const uint32_t da1 = sbase + r1 * ROWB + c1 * 16;

#define ISSUE(s, k0) do { \
        CP16(da0 + (s) * STAGE, arow0 + (k0)); \
        CP16(da1 + (s) * STAGE, arow1 + (k0)); \
        CP16(da0 + (s) * STAGE + ABYTES, brow0 + (k0)); \
        CP16(da1 + (s) * STAGE + ABYTES, brow1 + (k0)); \
        CP_COMMIT(); \
    } while (0)

    ISSUE(0, 0);
    ISSUE(1, KC);

    for (int i = 0; i < NCHUNK; i++) {
        const int p = i % 3;
        if (i + 2 < NCHUNK)      { ISSUE((i + 2) % 3, (i + 2) * KC); CP_WAIT(2); }
        else if (i + 1 < NCHUNK) { CP_WAIT(1); }
        else                     { CP_WAIT(0); }
        __syncthreads();

        const __half* As = (const __half*)(smraw + p * STAGE);
        const __half* Bs = (const __half*)(smraw + p * STAGE + ABYTES);
#pragma unroll
        for (int ks = 0; ks < KC; ks += 16) {
            wmma::fragment<wmma::matrix_a, 16, 16, 16, __half, wmma::row_major> a0, a1;
            wmma::load_matrix_sync(a0, &As[(wr * 32) * KCP2 + ks], KCP2);
            wmma::load_matrix_sync(a1, &As[(wr * 32 + 16) * KCP2 + ks], KCP2);
#pragma unroll
            for (int nn = 0; nn < 4; nn++) {
                wmma::fragment<wmma::matrix_b, 16, 16, 16, __half, wmma::col_major> b;
                wmma::load_matrix_sync(b, &Bs[(wc * 64 + nn * 16) * KCP2 + ks], KCP2);
                wmma::mma_sync(c[0][nn], a0, b, c[0][nn]);
                wmma::mma_sync(c[1][nn], a1, b, c[1][nn]);
            }
        }
        __syncthreads();
    }

    // epilogue: stage C as half, per-head RMSNorm, write scratch
    __half* Cs = (__half*)smraw;
#pragma unroll
    for (int i = 0; i < 2; i++)
#pragma unroll
        for (int nn = 0; nn < 4; nn++) {
            wmma::fragment<wmma::accumulator, 16, 16, 16, __half> ch;
#pragma unroll
            for (int e = 0; e < ch.num_elements; e++)
                ch.x[e] = __float2half_rn(c[i][nn].x[e]);
            wmma::store_matrix_sync(&Cs[(wr * 32 + i * 16) * CLD2 + wc * 64 + nn * 16],
                                    ch, CLD2, wmma::mem_row_major);
        }
    __syncthreads();

    __shared__ float sscale[BM * 2];
    {
        int row = t >> 1, g = t & 1;
        float s = 1.0f;
        if (mode != 2) {
            const __half* cr = &Cs[row * CLD2 + g * 64];
            float ss = 0.0f;
#pragma unroll
            for (int d = 0; d < 64; d++) { float v = __half2float(cr[d]); ss += v * v; }
            s = rsqrtf(ss * (1.0f / 64.0f) + 1e-6f);
            if (mode == 0) s *= 0.125f;
        }
        sscale[row * 2 + g] = s;
    }
    __syncthreads();

#pragma unroll
    for (int it = 0; it < 16; it++) {
        int f = t + it * 256;
        int row = f >> 5;
        int j = (f & 31) << 2;
        int g = j >> 6;
        int d = j & 63;
        int gi = m0 + row;
        int bb, n;
        if (mode == 0) { bb = gi >> 12; n = gi & 4095; }
        else           { bb = gi >> 9;  n = gi & 511;  }
        int h = (n0 >> 6) + g;
        float sc = sscale[row * 2 + g];
        const __half* cr = &Cs[row * CLD2 + j];
        __half o[4];
#pragma unroll
        for (int u = 0; u < 4; u++)
            o[u] = __float2half_rn(__half2float(cr[u]) * sc);
        if (mode == 2) {
#pragma unroll
            for (int u = 0; u < 4; u++)
                g_v[(((size_t)bb * NH + h) * HD + d + u) * NKV + n] = o[u];
        } else if (mode == 0) {
            *(uint2*)&g_q[(((size_t)bb * NH + h) * NQ + n) * HD + d] = *(uint2*)o;
        } else {
            *(uint2*)&g_k[(((size_t)bb * NH + h) * NKV + n) * HD + d] = *(uint2*)o;
        }
    }
}

// ===========================================================================
// FlashAttention-2 attention with cp.async double-buffered K/V tiles.
// (unchanged from R8 — known good)
// ===========================================================================
#define ATQ 64
#define KVT 64
#define TLD 72

__device__ __forceinline__ void mma16816(float* c, const uint32_t* a,
                                         uint32_t b0, uint32_t b1)
{
    asm volatile(
        "mma.sync.aligned.m16n8k16.row.col.f32.f16.f16.f32 "
        "{%0,%1,%2,%3}, {%4,%5,%6,%7}, {%8,%9}, {%0,%1,%2,%3};"
        : "+f"(c[0]), "+f"(c[1]), "+f"(c[2]), "+f"(c[3])
        : "r"(a[0]), "r"(a[1]), "r"(a[2]), "r"(a[3]), "r"(b0), "r"(b1));
}

__global__ __launch_bounds__(128) void attn_fa(float* __restrict__ out)
{
    __shared__ __half Ks[2][KVT * TLD];
    __shared__ __half Vs[2][HD * TLD];

    const int t = threadIdx.x;
    const int warp = t >> 5, lane = t & 31;
    const int group = lane >> 2, tig = lane & 3;
    const int q0 = blockIdx.x * ATQ;
    const int h = blockIdx.y, b = blockIdx.z;

    const __half* qbase = g_q + (((size_t)b * NH + h) * NQ + q0 + warp * 16) * HD;
    const __half* kbase = g_k + ((size_t)b * NH + h) * NKV * HD;
    const __half* vtbase = g_v + ((size_t)b * NH + h) * HD * NKV;

    uint32_t ksb, vsb;
    asm("{ .reg .u64 u; cvta.to.shared.u64 u, %1; cvt.u32.u64 %0, u; }" : "=r"(ksb) : "l"(&Ks[0][0]));
    asm("{ .reg .u64 u; cvta.to.shared.u64 u, %1; cvt.u32.u64 %0, u; }" : "=r"(vsb) : "l"(&Vs[0][0]));

    int rr[4], cc[4];
#pragma unroll
    for (int it = 0; it < 4; it++) {
        int f = t + it * 128;
        rr[it] = f >> 3;
        cc[it] = (f & 7) * 8;
    }

#define AISSUE(kt, p) do { \
        _Pragma("unroll") \
        for (int it = 0; it < 4; it++) { \
            CP16(ksb + ((p) * KVT * TLD + rr[it] * TLD + cc[it]) * 2, \
                 &kbase[((kt) * 64 + rr[it]) * HD + cc[it]]); \
            CP16(vsb + ((p) * HD * TLD + rr[it] * TLD + cc[it]) * 2, \
                 &vtbase[(size_t)rr[it] * NKV + (kt) * 64 + cc[it]]); \
        } \
        CP_COMMIT(); \
    } while (0)

    uint32_t qa[4][4];
    {
        const __half* qrA = qbase + group * HD;
        const __half* qrB = qbase + (group + 8) * HD;
#pragma unroll
        for (int i = 0; i < 4; i++) {
            qa[i][0] = *(const uint32_t*)&qrA[i * 16 + tig * 2];
            qa[i][1] = *(const uint32_t*)&qrB[i * 16 + tig * 2];
            qa[i][2] = *(const uint32_t*)&qrA[i * 16 + 8 + tig * 2];
            qa[i][3] = *(const uint32_t*)&qrB[i * 16 + 8 + tig * 2];
        }
    }

    AISSUE(0, 0);

    float o[8][4];
#pragma unroll
    for (int j = 0; j < 8; j++)
        o[j][0] = o[j][1] = o[j][2] = o[j][3] = 0.0f;
    float mA = -1e30f, mB = -1e30f, lA = 0.0f, lB = 0.0f;

    for (int kt = 0; kt < 8; kt++) {
        const int p = kt & 1;
        if (kt < 7) { AISSUE(kt + 1, p ^ 1); CP_WAIT(1); }
        else        { CP_WAIT(0); }
        __syncthreads();

        float s[8][4];
#pragma unroll
        for (int j = 0; j < 8; j++) {
            s[j][0] = s[j][1] = s[j][2] = s[j][3] = 0.0f;
            const __half* kr = &Ks[p][(j * 8 + group) * TLD + tig * 2];
#pragma unroll
            for (int i = 0; i < 4; i++) {
                uint32_t b0 = *(const uint32_t*)&kr[i * 16];
                uint32_t b1 = *(const uint32_t*)&kr[i * 16 + 8];
                mma16816(s[j], qa[i], b0, b1);
            }
        }

        float tAm = -1e30f, tBm = -1e30f;
#pragma unroll
        for (int j = 0; j < 8; j++) {
            tAm = fmaxf(tAm, fmaxf(s[j][0], s[j][1]));
            tBm = fmaxf(tBm, fmaxf(s[j][2], s[j][3]));
        }
        tAm = fmaxf(tAm, __shfl_xor_sync(0xffffffffu, tAm, 1));
        tAm = fmaxf(tAm, __shfl_xor_sync(0xffffffffu, tAm, 2));
        tBm = fmaxf(tBm, __shfl_xor_sync(0xffffffffu, tBm, 1));
        tBm = fmaxf(tBm, __shfl_xor_sync(0xffffffffu, tBm, 2));
        float nmA = fmaxf(mA, tAm), nmB = fmaxf(mB, tBm);
        float cA = __expf(mA - nmA), cB = __expf(mB - nmB);
        mA = nmA; mB = nmB;
        lA *= cA; lB *= cB;
#pragma unroll
        for (int j = 0; j < 8; j++) {
            o[j][0] *= cA; o[j][1] *= cA;
            o[j][2] *= cB; o[j][3] *= cB;
        }

        uint32_t ph[8][2];
        float sumA = 0.0f, sumB = 0.0f;
#pragma unroll
        for (int j = 0; j < 8; j++) {
            float e0 = __expf(s[j][0] - nmA);
            float e1 = __expf(s[j][1] - nmA);
            float e2 = __expf(s[j][2] - nmB);
            float e3 = __expf(s[j][3] - nmB);
            sumA += e0 + e1; sumB += e2 + e3;
            __half2 p01 = __floats2half2_rn(e0, e1);
            __half2 p23 = __floats2half2_rn(e2, e3);
            ph[j][0] = *(uint32_t*)&p01;
            ph[j][1] = *(uint32_t*)&p23;
        }
        lA += sumA; lB += sumB;

#pragma unroll
        for (int i2 = 0; i2 < 4; i2++) {
            uint32_t pa[4] = { ph[2 * i2][0], ph[2 * i2][1],
                               ph[2 * i2 + 1][0], ph[2 * i2 + 1][1] };
#pragma unroll
            for (int j3 = 0; j3 < 8; j3++) {
                const __half* vr = &Vs[p][(j3 * 8 + group) * TLD + tig * 2];
                uint32_t b0 = *(const uint32_t*)&vr[i2 * 16];
                uint32_t b1 = *(const uint32_t*)&vr[i2 * 16 + 8];
                mma16816(o[j3], pa, b0, b1);
            }
        }
        __syncthreads();
    }

    lA += __shfl_xor_sync(0xffffffffu, lA, 1);
    lA += __shfl_xor_sync(0xffffffffu, lA, 2);
    lB += __shfl_xor_sync(0xffffffffu, lB, 1);
    lB += __shfl_xor_sync(0xffffffffu, lB, 2);
    float rA = 1.0f / lA, rB = 1.0f / lB;

    float* obase = out + ((size_t)b * NQ + q0 + warp * 16) * DIM + h * HD;
#pragma unroll
    for (int j3 = 0; j3 < 8; j3++) {
        float2 vA = { o[j3][0] * rA, o[j3][1] * rA };
        float2 vB = { o[j3][2] * rB, o[j3][3] * rB };
        *(float2*)&obase[(size_t)group * DIM + j3 * 8 + tig * 2] = vA;
        *(float2*)&obase[(size_t)(group + 8) * DIM + j3 * 8 + tig * 2] = vB;
    }
}

// ---------------------------------------------------------------------------
extern "C" void kernel_launch(void* const* d_in, const int* in_sizes, int n_in,
                              void* d_out, int out_size)
{
    const float* x  = (const float*)d_in[0];
    const float* cx = (const float*)d_in[1];
    const float* Wq = (const float*)d_in[2];
    const float* Wk = (const float*)d_in[3];
    const float* Wv = (const float*)d_in[4];
    float* out = (float*)d_out;

    cudaFuncSetAttribute((const void*)proj_all,
                         cudaFuncAttributeMaxDynamicSharedMemorySize, PROJ_SMEM);

    // fused conversion prepass (one launch)
    conv_all<<<CONV_BLOCKS, 256>>>(x, cx, Wq, Wk, Wv);
    // fused q/k/v projections (one launch, 1280 CTAs)
    proj_all<<<1280, 256, PROJ_SMEM>>>();
    // fused attention
    attn_fa<<<dim3(NQ / ATQ, NH, NB), 128>>>(out);
}

// round 10
// speedup vs baseline: 1.2355x; 1.0174x over previous
#include <cuda_runtime.h>
#include <cuda_fp16.h>
#include <cstdint>
#include <mma.h>
using namespace nvcuda;

#define DIM 2048
#define NH 32
#define HD 64
#define NB 2
#define NQ 4096
#define NKV 512

// -------- device scratch (allocation-free rule) --------
__device__ __half h_x [(size_t)NB * NQ  * DIM];
__device__ __half h_cx[(size_t)NB * NKV * DIM];
__device__ __half h_wq[(size_t)DIM * DIM];
__device__ __half h_wk[(size_t)DIM * DIM];        // gathered rows h*128+2d
__device__ __half h_wv[(size_t)DIM * DIM];        // gathered rows h*128+2d+1
__device__ __half g_q[(size_t)NB * NH * NQ  * HD]; // rmsnorm(q) * 0.125 * log2(e)
__device__ __half g_k[(size_t)NB * NH * NKV * HD];
__device__ __half g_v[(size_t)NB * NH * HD * NKV]; // (b,h,d,m) transposed

// ===========================================================================
// Fused conversion prepass — one launch.
// ===========================================================================
#define CONV_BLOCKS 26624

__global__ __launch_bounds__(256) void conv_all(
    const float* __restrict__ x, const float* __restrict__ cx,
    const float* __restrict__ Wq, const float* __restrict__ Wk,
    const float* __restrict__ Wv)
{
    const int bid = blockIdx.x;
    const int t = threadIdx.x;
    if (bid < 22528) {
        const float* src;
        __half* dst;
        size_t i;
        if (bid < 16384)      { src = x;  dst = h_x;  i = ((size_t)bid * 256 + t) * 4; }
        else if (bid < 18432) { src = cx; dst = h_cx; i = ((size_t)(bid - 16384) * 256 + t) * 4; }
        else                  { src = Wq; dst = h_wq; i = ((size_t)(bid - 18432) * 256 + t) * 4; }
        float4 v = *(const float4*)&src[i];
        __half o[4] = { __float2half_rn(v.x), __float2half_rn(v.y),
                        __float2half_rn(v.z), __float2half_rn(v.w) };
        *(uint2*)&dst[i] = *(uint2*)o;
    } else {
        int i = bid - 22528;
        int j = i >> 1;
        int c = ((i & 1) * 256 + t) * 4;
        int h = j >> 6, d = j & 63;
        int g = h * 128 + 2 * d;
        const float* srcK = (g < DIM) ? (Wk + (size_t)g * DIM) : (Wv + (size_t)(g - DIM) * DIM);
        const float* srcV = (g + 1 < DIM) ? (Wk + (size_t)(g + 1) * DIM)
                                          : (Wv + (size_t)(g + 1 - DIM) * DIM);
        float4 vk = *(const float4*)&srcK[c];
        float4 vv = *(const float4*)&srcV[c];
        __half ok[4] = { __float2half_rn(vk.x), __float2half_rn(vk.y),
                         __float2half_rn(vk.z), __float2half_rn(vk.w) };
        __half ov[4] = { __float2half_rn(vv.x), __float2half_rn(vv.y),
                         __float2half_rn(vv.z), __float2half_rn(vv.w) };
        *(uint2*)&h_wk[(size_t)j * DIM + c] = *(uint2*)ok;
        *(uint2*)&h_wv[(size_t)j * DIM + c] = *(uint2*)ov;
    }
}

// common cp.async macros
#define CP16(d, s) asm volatile("cp.async.cg.shared.global [%0], [%1], 16;" :: "r"(d), "l"(s))
#define CP_COMMIT() asm volatile("cp.async.commit_group;" ::: "memory")
#define CP_WAIT(n)  asm volatile("cp.async.wait_group %0;" :: "n"(n) : "memory")

#define KC 32
#define KCP2 40
#define ROWB 80
#define CLD2 136
#define NCHUNK (DIM / KC)

#define BM 128
#define ABYTES (BM * ROWB)            // 10240
#define STAGE (2 * ABYTES)            // 20480
#define PROJ_SMEM (3 * STAGE)         // 61440, 3-stage; 2 CTAs/SM

// q scale: 1/8 (softmax) * log2(e) (for ex2-based exp)
#define QSCALE 0.18033688011112042f

// ===========================================================================
// Fused projection GEMM — one 1280-CTA launch (R9, known good).
// ===========================================================================
__global__ __launch_bounds__(256, 2) void proj_all()
{
    extern __shared__ char smraw[];
    uint32_t sbase;
    asm("{ .reg .u64 t; cvta.to.shared.u64 t, %1; cvt.u32.u64 %0, t; }"
        : "=r"(sbase) : "l"(smraw));

    int mode, mt, nt;
    const __half *A, *Bm;
    {
        int bid = blockIdx.x;
        if (bid < 256) {
            int i = bid >> 1;
            mode = 1 + (bid & 1);
            mt = i & 7; nt = i >> 3;
            A = h_cx; Bm = (mode == 1) ? h_wk : h_wv;
        } else {
            int i = bid - 256;
            mode = 0;
            mt = i & 63; nt = i >> 6;
            A = h_x; Bm = h_wq;
        }
    }
    const int m0 = mt * BM;
    const int n0 = nt * BM;
    const int t = threadIdx.x;
    const int warp = t >> 5;
    const int wr = warp & 3;
    const int wc = warp >> 2;

    wmma::fragment<wmma::accumulator, 16, 16, 16, float> c[2][4];
#pragma unroll
    for (int i = 0; i < 2; i++)
#pragma unroll
        for (int j = 0; j < 4; j++) wmma::fill_fragment(c[i][j], 0.0f);

    const int r0 = t >> 2, c0 = t & 3;
    const int r1 = (t + 256) >> 2, c1 = (t + 256) & 3;
    const __half* arow0 = A + (size_t)(m0 + r0) * DIM + c0 * 8;
    const __half* arow1 = A + (size_t)(m0 + r1) * DIM + c1 * 8;
    const __half* brow0 = Bm + (size_t)(n0 + r0) * DIM + c0 * 8;
    const __half* brow1 = Bm + (size_t)(n0 + r1) * DIM + c1 * 8;
    const uint32_t da0 = sbase + r0 * ROWB + c0 * 16;
    const uint32_t da1 = sbase + r1 * ROWB + c1 * 16;

#define ISSUE(s, k0) do { \
        CP16(da0 + (s) * STAGE, arow0 + (k0)); \
        CP16(da1 + (s) * STAGE, arow1 + (k0)); \
        CP16(da0 + (s) * STAGE + ABYTES, brow0 + (k0)); \
        CP16(da1 + (s) * STAGE + ABYTES, brow1 + (k0)); \
        CP_COMMIT(); \
    } while (0)

    ISSUE(0, 0);
    ISSUE(1, KC);

    for (int i = 0; i < NCHUNK; i++) {
        const int p = i % 3;
        if (i + 2 < NCHUNK)      { ISSUE((i + 2) % 3, (i + 2) * KC); CP_WAIT(2); }
        else if (i + 1 < NCHUNK) { CP_WAIT(1); }
        else                     { CP_WAIT(0); }
        __syncthreads();

        const __half* As = (const __half*)(smraw + p * STAGE);
        const __half* Bs = (const __half*)(smraw + p * STAGE + ABYTES);
#pragma unroll
        for (int ks = 0; ks < KC; ks += 16) {
            wmma::fragment<wmma::matrix_a, 16, 16, 16, __half, wmma::row_major> a0, a1;
            wmma::load_matrix_sync(a0, &As[(wr * 32) * KCP2 + ks], KCP2);
            wmma::load_matrix_sync(a1, &As[(wr * 32 + 16) * KCP2 + ks], KCP2);
#pragma unroll
            for (int nn = 0; nn < 4; nn++) {
                wmma::fragment<wmma::matrix_b, 16, 16, 16, __half, wmma::col_major> b;
                wmma::load_matrix_sync(b, &Bs[(wc * 64 + nn * 16) * KCP2 + ks], KCP2);
                wmma::mma_sync(c[0][nn], a0, b, c[0][nn]);
                wmma::mma_sync(c[1][nn], a1, b, c[1][nn]);
            }
        }
        __syncthreads();
    }

    __half* Cs = (__half*)smraw;
#pragma unroll
    for (int i = 0; i < 2; i++)
#pragma unroll
        for (int nn = 0; nn < 4; nn++) {
            wmma::fragment<wmma::accumulator, 16, 16, 16, __half> ch;
#pragma unroll
            for (int e = 0; e < ch.num_elements; e++)
                ch.x[e] = __float2half_rn(c[i][nn].x[e]);
            wmma::store_matrix_sync(&Cs[(wr * 32 + i * 16) * CLD2 + wc * 64 + nn * 16],
                                    ch, CLD2, wmma::mem_row_major);
        }
    __syncthreads();

    __shared__ float sscale[BM * 2];
    {
        int row = t >> 1, g = t & 1;
        float s = 1.0f;
        if (mode != 2) {
            const __half* cr = &Cs[row * CLD2 + g * 64];
            float ss = 0.0f;
#pragma unroll
            for (int d = 0; d < 64; d++) { float v = __half2float(cr[d]); ss += v * v; }
            s = rsqrtf(ss * (1.0f / 64.0f) + 1e-6f);
            if (mode == 0) s *= QSCALE;   // 1/8 * log2(e) folded into q
        }
        sscale[row * 2 + g] = s;
    }
    __syncthreads();

#pragma unroll
    for (int it = 0; it < 16; it++) {
        int f = t + it * 256;
        int row = f >> 5;
        int j = (f & 31) << 2;
        int g = j >> 6;
        int d = j & 63;
        int gi = m0 + row;
        int bb, n;
        if (mode == 0) { bb = gi >> 12; n = gi & 4095; }
        else           { bb = gi >> 9;  n = gi & 511;  }
        int h = (n0 >> 6) + g;
        float sc = sscale[row * 2 + g];
        const __half* cr = &Cs[row * CLD2 + j];
        __half o[4];
#pragma unroll
        for (int u = 0; u < 4; u++)
            o[u] = __float2half_rn(__half2float(cr[u]) * sc);
        if (mode == 2) {
#pragma unroll
            for (int u = 0; u < 4; u++)
                g_v[(((size_t)bb * NH + h) * HD + d + u) * NKV + n] = o[u];
        } else if (mode == 0) {
            *(uint2*)&g_q[(((size_t)bb * NH + h) * NQ + n) * HD + d] = *(uint2*)o;
        } else {
            *(uint2*)&g_k[(((size_t)bb * NH + h) * NKV + n) * HD + d] = *(uint2*)o;
        }
    }
}

// ===========================================================================
// FlashAttention attention, NO-MAX softmax:
// scores pre-scaled by log2e/8, |logit| <= 8 guaranteed by rmsnorm
// (|q_row|=1, |k_row|=8, Cauchy-Schwarz) -> exp(s) <= e^8 = 2981 < half max.
// P = 2^s via single MUFU; divide by running sum at the end.
// ===========================================================================
#define ATQ 64
#define KVT 64
#define TLD 72

__device__ __forceinline__ void mma16816(float* c, const uint32_t* a,
                                         uint32_t b0, uint32_t b1)
{
    asm volatile(
        "mma.sync.aligned.m16n8k16.row.col.f32.f16.f16.f32 "
        "{%0,%1,%2,%3}, {%4,%5,%6,%7}, {%8,%9}, {%0,%1,%2,%3};"
        : "+f"(c[0]), "+f"(c[1]), "+f"(c[2]), "+f"(c[3])
        : "r"(a[0]), "r"(a[1]), "r"(a[2]), "r"(a[3]), "r"(b0), "r"(b1));
}

__device__ __forceinline__ float ex2(float x)
{
    float r;
    asm("ex2.approx.ftz.f32 %0, %1;" : "=f"(r) : "f"(x));
    return r;
}

__global__ __launch_bounds__(128) void attn_fa(float* __restrict__ out)
{
    __shared__ __half Ks[2][KVT * TLD];
    __shared__ __half Vs[2][HD * TLD];

    const int t = threadIdx.x;
    const int warp = t >> 5, lane = t & 31;
    const int group = lane >> 2, tig = lane & 3;
    const int q0 = blockIdx.x * ATQ;
    const int h = blockIdx.y, b = blockIdx.z;

    const __half* qbase = g_q + (((size_t)b * NH + h) * NQ + q0 + warp * 16) * HD;
    const __half* kbase = g_k + ((size_t)b * NH + h) * NKV * HD;
    const __half* vtbase = g_v + ((size_t)b * NH + h) * HD * NKV;

    uint32_t ksb, vsb;
    asm("{ .reg .u64 u; cvta.to.shared.u64 u, %1; cvt.u32.u64 %0, u; }" : "=r"(ksb) : "l"(&Ks[0][0]));
    asm("{ .reg .u64 u; cvta.to.shared.u64 u, %1; cvt.u32.u64 %0, u; }" : "=r"(vsb) : "l"(&Vs[0][0]));

    int rr[4], cc[4];
#pragma unroll
    for (int it = 0; it < 4; it++) {
        int f = t + it * 128;
        rr[it] = f >> 3;
        cc[it] = (f & 7) * 8;
    }

#define AISSUE(kt, p) do { \
        _Pragma("unroll") \
        for (int it = 0; it < 4; it++) { \
            CP16(ksb + ((p) * KVT * TLD + rr[it] * TLD + cc[it]) * 2, \
                 &kbase[((kt) * 64 + rr[it]) * HD + cc[it]]); \
            CP16(vsb + ((p) * HD * TLD + rr[it] * TLD + cc[it]) * 2, \
                 &vtbase[(size_t)rr[it] * NKV + (kt) * 64 + cc[it]]); \
        } \
        CP_COMMIT(); \
    } while (0)

    uint32_t qa[4][4];
    {
        const __half* qrA = qbase + group * HD;
        const __half* qrB = qbase + (group + 8) * HD;
#pragma unroll
        for (int i = 0; i < 4; i++) {
            qa[i][0] = *(const uint32_t*)&qrA[i * 16 + tig * 2];
            qa[i][1] = *(const uint32_t*)&qrB[i * 16 + tig * 2];
            qa[i][2] = *(const uint32_t*)&qrA[i * 16 + 8 + tig * 2];
            qa[i][3] = *(const uint32_t*)&qrB[i * 16 + 8 + tig * 2];
        }
    }

    AISSUE(0, 0);

    float o[8][4];
#pragma unroll
    for (int j = 0; j < 8; j++)
        o[j][0] = o[j][1] = o[j][2] = o[j][3] = 0.0f;
    float lA = 0.0f, lB = 0.0f;

    for (int kt = 0; kt < 8; kt++) {
        const int p = kt & 1;
        if (kt < 7) { AISSUE(kt + 1, p ^ 1); CP_WAIT(1); }
        else        { CP_WAIT(0); }
        __syncthreads();

        // S = Q K^T (scores already in log2 domain)
        float s[8][4];
#pragma unroll
        for (int j = 0; j < 8; j++) {
            s[j][0] = s[j][1] = s[j][2] = s[j][3] = 0.0f;
            const __half* kr = &Ks[p][(j * 8 + group) * TLD + tig * 2];
#pragma unroll
            for (int i = 0; i < 4; i++) {
                uint32_t b0 = *(const uint32_t*)&kr[i * 16];
                uint32_t b1 = *(const uint32_t*)&kr[i * 16 + 8];
                mma16816(s[j], qa[i], b0, b1);
            }
        }

        // P = 2^S, accumulate row sums; no max, no rescale
        uint32_t ph[8][2];
        float sumA = 0.0f, sumB = 0.0f;
#pragma unroll
        for (int j = 0; j < 8; j++) {
            float e0 = ex2(s[j][0]);
            float e1 = ex2(s[j][1]);
            float e2 = ex2(s[j][2]);
            float e3 = ex2(s[j][3]);
            sumA += e0 + e1; sumB += e2 + e3;
            __half2 p01 = __floats2half2_rn(e0, e1);
            __half2 p23 = __floats2half2_rn(e2, e3);
            ph[j][0] = *(uint32_t*)&p01;
            ph[j][1] = *(uint32_t*)&p23;
        }
        lA += sumA; lB += sumB;

        // O += P V
#pragma unroll
        for (int i2 = 0; i2 < 4; i2++) {
            uint32_t pa[4] = { ph[2 * i2][0], ph[2 * i2][1],
                               ph[2 * i2 + 1][0], ph[2 * i2 + 1][1] };
#pragma unroll
            for (int j3 = 0; j3 < 8; j3++) {
                const __half* vr = &Vs[p][(j3 * 8 + group) * TLD + tig * 2];
                uint32_t b0 = *(const uint32_t*)&vr[i2 * 16];
                uint32_t b1 = *(const uint32_t*)&vr[i2 * 16 + 8];
                mma16816(o[j3], pa, b0, b1);
            }
        }
        __syncthreads();
    }

    lA += __shfl_xor_sync(0xffffffffu, lA, 1);
    lA += __shfl_xor_sync(0xffffffffu, lA, 2);
    lB += __shfl_xor_sync(0xffffffffu, lB, 1);
    lB += __shfl_xor_sync(0xffffffffu, lB, 2);
    float rA = 1.0f / lA, rB = 1.0f / lB;

    float* obase = out + ((size_t)b * NQ + q0 + warp * 16) * DIM + h * HD;
#pragma unroll
    for (int j3 = 0; j3 < 8; j3++) {
        float2 vA = { o[j3][0] * rA, o[j3][1] * rA };
        float2 vB = { o[j3][2] * rB, o[j3][3] * rB };
        *(float2*)&obase[(size_t)group * DIM + j3 * 8 + tig * 2] = vA;
        *(float2*)&obase[(size_t)(group + 8) * DIM + j3 * 8 + tig * 2] = vB;
    }
}

// ---------------------------------------------------------------------------
extern "C" void kernel_launch(void* const* d_in, const int* in_sizes, int n_in,
                              void* d_out, int out_size)
{
    const float* x  = (const float*)d_in[0];
    const float* cx = (const float*)d_in[1];
    const float* Wq = (const float*)d_in[2];
    const float* Wk = (const float*)d_in[3];
    const float* Wv = (const float*)d_in[4];
    float* out = (float*)d_out;

    cudaFuncSetAttribute((const void*)proj_all,
                         cudaFuncAttributeMaxDynamicSharedMemorySize, PROJ_SMEM);

    conv_all<<<CONV_BLOCKS, 256>>>(x, cx, Wq, Wk, Wv);
    proj_all<<<1280, 256, PROJ_SMEM>>>();
    attn_fa<<<dim3(NQ / ATQ, NH, NB), 128>>>(out);
}

// round 11
// speedup vs baseline: 1.2683x; 1.0266x over previous
#include <cuda_runtime.h>
#include <cuda_fp16.h>
#include <cstdint>
#include <mma.h>
using namespace nvcuda;

#define DIM 2048
#define NH 32
#define HD 64
#define NB 2
#define NQ 4096
#define NKV 512

// -------- device scratch (allocation-free rule) --------
__device__ __half h_x [(size_t)NB * NQ  * DIM];
__device__ __half h_cx[(size_t)NB * NKV * DIM];
__device__ __half h_wq[(size_t)DIM * DIM];
__device__ __half h_wk[(size_t)DIM * DIM];        // gathered rows h*128+2d
__device__ __half h_wv[(size_t)DIM * DIM];        // gathered rows h*128+2d+1
__device__ __half g_q[(size_t)NB * NH * NQ  * HD]; // rmsnorm(q) * 0.125 * log2(e)
__device__ __half g_k[(size_t)NB * NH * NKV * HD];
__device__ __half g_v[(size_t)NB * NH * HD * NKV]; // (b,h,d,m) transposed

// ===========================================================================
// Fused conversion prepass — one launch (R9, known good).
// ===========================================================================
#define CONV_BLOCKS 26624

__global__ __launch_bounds__(256) void conv_all(
    const float* __restrict__ x, const float* __restrict__ cx,
    const float* __restrict__ Wq, const float* __restrict__ Wk,
    const float* __restrict__ Wv)
{
    const int bid = blockIdx.x;
    const int t = threadIdx.x;
    if (bid < 22528) {
        const float* src;
        __half* dst;
        size_t i;
        if (bid < 16384)      { src = x;  dst = h_x;  i = ((size_t)bid * 256 + t) * 4; }
        else if (bid < 18432) { src = cx; dst = h_cx; i = ((size_t)(bid - 16384) * 256 + t) * 4; }
        else                  { src = Wq; dst = h_wq; i = ((size_t)(bid - 18432) * 256 + t) * 4; }
        float4 v = *(const float4*)&src[i];
        __half o[4] = { __float2half_rn(v.x), __float2half_rn(v.y),
                        __float2half_rn(v.z), __float2half_rn(v.w) };
        *(uint2*)&dst[i] = *(uint2*)o;
    } else {
        int i = bid - 22528;
        int j = i >> 1;
        int c = ((i & 1) * 256 + t) * 4;
        int h = j >> 6, d = j & 63;
        int g = h * 128 + 2 * d;
        const float* srcK = (g < DIM) ? (Wk + (size_t)g * DIM) : (Wv + (size_t)(g - DIM) * DIM);
        const float* srcV = (g + 1 < DIM) ? (Wk + (size_t)(g + 1) * DIM)
                                          : (Wv + (size_t)(g + 1 - DIM) * DIM);
        float4 vk = *(const float4*)&srcK[c];
        float4 vv = *(const float4*)&srcV[c];
        __half ok[4] = { __float2half_rn(vk.x), __float2half_rn(vk.y),
                         __float2half_rn(vk.z), __float2half_rn(vk.w) };
        __half ov[4] = { __float2half_rn(vv.x), __float2half_rn(vv.y),
                         __float2half_rn(vv.z), __float2half_rn(vv.w) };
        *(uint2*)&h_wk[(size_t)j * DIM + c] = *(uint2*)ok;
        *(uint2*)&h_wv[(size_t)j * DIM + c] = *(uint2*)ov;
    }
}

// common cp.async macros
#define CP16(d, s) asm volatile("cp.async.cg.shared.global [%0], [%1], 16;" :: "r"(d), "l"(s))
#define CP_COMMIT() asm volatile("cp.async.commit_group;" ::: "memory")
#define CP_WAIT(n)  asm volatile("cp.async.wait_group %0;" :: "n"(n) : "memory")

#define KC 32
#define KCP2 40
#define ROWB 80
#define CLD2 136
#define NCHUNK (DIM / KC)

#define BM 128
#define ABYTES (BM * ROWB)            // 10240
#define STAGE (2 * ABYTES)            // 20480
#define PROJ_SMEM (3 * STAGE)         // 61440, 3-stage; 2 CTAs/SM

// q scale: 1/8 (softmax) * log2(e) (for ex2-based exp)
#define QSCALE 0.18033688011112042f

// ===========================================================================
// Fused projection GEMM — one 1280-CTA launch (R9, known good).
// ===========================================================================
__global__ __launch_bounds__(256, 2) void proj_all()
{
    extern __shared__ char smraw[];
    uint32_t sbase;
    asm("{ .reg .u64 t; cvta.to.shared.u64 t, %1; cvt.u32.u64 %0, t; }"
        : "=r"(sbase) : "l"(smraw));

    int mode, mt, nt;
    const __half *A, *Bm;
    {
        int bid = blockIdx.x;
        if (bid < 256) {
            int i = bid >> 1;
            mode = 1 + (bid & 1);
            mt = i & 7; nt = i >> 3;
            A = h_cx; Bm = (mode == 1) ? h_wk : h_wv;
        } else {
            int i = bid - 256;
            mode = 0;
            mt = i & 63; nt = i >> 6;
            A = h_x; Bm = h_wq;
        }
    }
    const int m0 = mt * BM;
    const int n0 = nt * BM;
    const int t = threadIdx.x;
    const int warp = t >> 5;
    const int wr = warp & 3;
    const int wc = warp >> 2;

    wmma::fragment<wmma::accumulator, 16, 16, 16, float> c[2][4];
#pragma unroll
    for (int i = 0; i < 2; i++)
#pragma unroll
        for (int j = 0; j < 4; j++) wmma::fill_fragment(c[i][j], 0.0f);

    const int r0 = t >> 2, c0 = t & 3;
    const int r1 = (t + 256) >> 2, c1 = (t + 256) & 3;
    const __half* arow0 = A + (size_t)(m0 + r0) * DIM + c0 * 8;
    const __half* arow1 = A + (size_t)(m0 + r1) * DIM + c1 * 8;
    const __half* brow0 = Bm + (size_t)(n0 + r0) * DIM + c0 * 8;
    const __half* brow1 = Bm + (size_t)(n0 + r1) * DIM + c1 * 8;
    const uint32_t da0 = sbase + r0 * ROWB + c0 * 16;
    const uint32_t da1 = sbase + r1 * ROWB + c1 * 16;

#define ISSUE(s, k0) do { \
        CP16(da0 + (s) * STAGE, arow0 + (k0)); \
        CP16(da1 + (s) * STAGE, arow1 + (k0)); \
        CP16(da0 + (s) * STAGE + ABYTES, brow0 + (k0)); \
        CP16(da1 + (s) * STAGE + ABYTES, brow1 + (k0)); \
        CP_COMMIT(); \
    } while (0)

    ISSUE(0, 0);
    ISSUE(1, KC);

    for (int i = 0; i < NCHUNK; i++) {
        const int p = i % 3;
        if (i + 2 < NCHUNK)      { ISSUE((i + 2) % 3, (i + 2) * KC); CP_WAIT(2); }
        else if (i + 1 < NCHUNK) { CP_WAIT(1); }
        else                     { CP_WAIT(0); }
        __syncthreads();

        const __half* As = (const __half*)(smraw + p * STAGE);
        const __half* Bs = (const __half*)(smraw + p * STAGE + ABYTES);
#pragma unroll
        for (int ks = 0; ks < KC; ks += 16) {
            wmma::fragment<wmma::matrix_a, 16, 16, 16, __half, wmma::row_major> a0, a1;
            wmma::load_matrix_sync(a0, &As[(wr * 32) * KCP2 + ks], KCP2);
            wmma::load_matrix_sync(a1, &As[(wr * 32 + 16) * KCP2 + ks], KCP2);
#pragma unroll
            for (int nn = 0; nn < 4; nn++) {
                wmma::fragment<wmma::matrix_b, 16, 16, 16, __half, wmma::col_major> b;
                wmma::load_matrix_sync(b, &Bs[(wc * 64 + nn * 16) * KCP2 + ks], KCP2);
                wmma::mma_sync(c[0][nn], a0, b, c[0][nn]);
                wmma::mma_sync(c[1][nn], a1, b, c[1][nn]);
            }
        }
        __syncthreads();
    }

    __half* Cs = (__half*)smraw;
#pragma unroll
    for (int i = 0; i < 2; i++)
#pragma unroll
        for (int nn = 0; nn < 4; nn++) {
            wmma::fragment<wmma::accumulator, 16, 16, 16, __half> ch;
#pragma unroll
            for (int e = 0; e < ch.num_elements; e++)
                ch.x[e] = __float2half_rn(c[i][nn].x[e]);
            wmma::store_matrix_sync(&Cs[(wr * 32 + i * 16) * CLD2 + wc * 64 + nn * 16],
                                    ch, CLD2, wmma::mem_row_major);
        }
    __syncthreads();

    __shared__ float sscale[BM * 2];
    {
        int row = t >> 1, g = t & 1;
        float s = 1.0f;
        if (mode != 2) {
            const __half* cr = &Cs[row * CLD2 + g * 64];
            float ss = 0.0f;
#pragma unroll
            for (int d = 0; d < 64; d++) { float v = __half2float(cr[d]); ss += v * v; }
            s = rsqrtf(ss * (1.0f / 64.0f) + 1e-6f);
            if (mode == 0) s *= QSCALE;
        }
        sscale[row * 2 + g] = s;
    }
    __syncthreads();

#pragma unroll
    for (int it = 0; it < 16; it++) {
        int f = t + it * 256;
        int row = f >> 5;
        int j = (f & 31) << 2;
        int g = j >> 6;
        int d = j & 63;
        int gi = m0 + row;
        int bb, n;
        if (mode == 0) { bb = gi >> 12; n = gi & 4095; }
        else           { bb = gi >> 9;  n = gi & 511;  }
        int h = (n0 >> 6) + g;
        float sc = sscale[row * 2 + g];
        const __half* cr = &Cs[row * CLD2 + j];
        __half o[4];
#pragma unroll
        for (int u = 0; u < 4; u++)
            o[u] = __float2half_rn(__half2float(cr[u]) * sc);
        if (mode == 2) {
#pragma unroll
            for (int u = 0; u < 4; u++)
                g_v[(((size_t)bb * NH + h) * HD + d + u) * NKV + n] = o[u];
        } else if (mode == 0) {
            *(uint2*)&g_q[(((size_t)bb * NH + h) * NQ + n) * HD + d] = *(uint2*)o;
        } else {
            *(uint2*)&g_k[(((size_t)bb * NH + h) * NKV + n) * HD + d] = *(uint2*)o;
        }
    }
}

// ===========================================================================
// FlashAttention attention, no-max softmax, ldmatrix.x4 fragment loads.
// K/V fragments come via ldmatrix.m8n8.x4: conflict-free (row stride 144 B
// maps 8 rows to word-banks 4r+c, covering all 32 banks), 4x fewer LSU ops.
// ===========================================================================
#define ATQ 64
#define KVT 64
#define TLD 72
#define KVBYTES (KVT * TLD * 2)   // 9216 per buffer

__device__ __forceinline__ void mma16816(float* c, const uint32_t* a,
                                         uint32_t b0, uint32_t b1)
{
    asm volatile(
        "mma.sync.aligned.m16n8k16.row.col.f32.f16.f16.f32 "
        "{%0,%1,%2,%3}, {%4,%5,%6,%7}, {%8,%9}, {%0,%1,%2,%3};"
        : "+f"(c[0]), "+f"(c[1]), "+f"(c[2]), "+f"(c[3])
        : "r"(a[0]), "r"(a[1]), "r"(a[2]), "r"(a[3]), "r"(b0), "r"(b1));
}

__device__ __forceinline__ void ldsm4(uint32_t* b, uint32_t addr)
{
    asm volatile("ldmatrix.sync.aligned.m8n8.x4.shared.b16 {%0,%1,%2,%3}, [%4];"
                 : "=r"(b[0]), "=r"(b[1]), "=r"(b[2]), "=r"(b[3]) : "r"(addr));
}

__device__ __forceinline__ float ex2(float x)
{
    float r;
    asm("ex2.approx.ftz.f32 %0, %1;" : "=f"(r) : "f"(x));
    return r;
}

__global__ __launch_bounds__(128, 4) void attn_fa(float* __restrict__ out)
{
    __shared__ __half Ks[2][KVT * TLD];
    __shared__ __half Vs[2][HD * TLD];

    const int t = threadIdx.x;
    const int warp = t >> 5, lane = t & 31;
    const int group = lane >> 2, tig = lane & 3;
    const int q0 = blockIdx.x * ATQ;
    const int h = blockIdx.y, b = blockIdx.z;

    const __half* qbase = g_q + (((size_t)b * NH + h) * NQ + q0 + warp * 16) * HD;
    const __half* kbase = g_k + ((size_t)b * NH + h) * NKV * HD;
    const __half* vtbase = g_v + ((size_t)b * NH + h) * HD * NKV;

    uint32_t ksb, vsb;
    asm("{ .reg .u64 u; cvta.to.shared.u64 u, %1; cvt.u32.u64 %0, u; }" : "=r"(ksb) : "l"(&Ks[0][0]));
    asm("{ .reg .u64 u; cvta.to.shared.u64 u, %1; cvt.u32.u64 %0, u; }" : "=r"(vsb) : "l"(&Vs[0][0]));

    // ldmatrix per-lane offset: matrix = lane>>3 (k-chunk of 8), row = lane&7
    const uint32_t lm_off = ((uint32_t)(lane & 7) * TLD + (uint32_t)(lane >> 3) * 8) * 2;

    int rr[4], cc[4];
#pragma unroll
    for (int it = 0; it < 4; it++) {
        int f = t + it * 128;
        rr[it] = f >> 3;
        cc[it] = (f & 7) * 8;
    }

#define AISSUE(kt, p) do { \
        _Pragma("unroll") \
        for (int it = 0; it < 4; it++) { \
            CP16(ksb + (p) * KVBYTES + (rr[it] * TLD + cc[it]) * 2, \
                 &kbase[((kt) * 64 + rr[it]) * HD + cc[it]]); \
            CP16(vsb + (p) * KVBYTES + (rr[it] * TLD + cc[it]) * 2, \
                 &vtbase[(size_t)rr[it] * NKV + (kt) * 64 + cc[it]]); \
        } \
        CP_COMMIT(); \
    } while (0)

    uint32_t qa[4][4];
    {
        const __half* qrA = qbase + group * HD;
        const __half* qrB = qbase + (group + 8) * HD;
#pragma unroll
        for (int i = 0; i < 4; i++) {
            qa[i][0] = *(const uint32_t*)&qrA[i * 16 + tig * 2];
            qa[i][1] = *(const uint32_t*)&qrB[i * 16 + tig * 2];
            qa[i][2] = *(const uint32_t*)&qrA[i * 16 + 8 + tig * 2];
            qa[i][3] = *(const uint32_t*)&qrB[i * 16 + 8 + tig * 2];
        }
    }

    AISSUE(0, 0);

    float o[8][4];
#pragma unroll
    for (int j = 0; j < 8; j++)
        o[j][0] = o[j][1] = o[j][2] = o[j][3] = 0.0f;
    float lA = 0.0f, lB = 0.0f;

    for (int kt = 0; kt < 8; kt++) {
        const int p = kt & 1;
        if (kt < 7) { AISSUE(kt + 1, p ^ 1); CP_WAIT(1); }
        else        { CP_WAIT(0); }
        __syncthreads();

        // S = Q K^T  (B frags via ldmatrix: LDSM#0 k-cols {0,8,16,24}, #1 +32)
        float s[8][4];
#pragma unroll
        for (int j = 0; j < 8; j++) {
            s[j][0] = s[j][1] = s[j][2] = s[j][3] = 0.0f;
            uint32_t base = ksb + p * KVBYTES + (uint32_t)(j * 8 * TLD) * 2 + lm_off;
            uint32_t bm[4];
            ldsm4(bm, base);
            mma16816(s[j], qa[0], bm[0], bm[1]);
            mma16816(s[j], qa[1], bm[2], bm[3]);
            ldsm4(bm, base + 64);
            mma16816(s[j], qa[2], bm[0], bm[1]);
            mma16816(s[j], qa[3], bm[2], bm[3]);
        }

        // P = 2^S, accumulate row sums; no max, no rescale
        uint32_t ph[8][2];
        float sumA = 0.0f, sumB = 0.0f;
#pragma unroll
        for (int j = 0; j < 8; j++) {
            float e0 = ex2(s[j][0]);
            float e1 = ex2(s[j][1]);
            float e2 = ex2(s[j][2]);
            float e3 = ex2(s[j][3]);
            sumA += e0 + e1; sumB += e2 + e3;
            __half2 p01 = __floats2half2_rn(e0, e1);
            __half2 p23 = __floats2half2_rn(e2, e3);
            ph[j][0] = *(uint32_t*)&p01;
            ph[j][1] = *(uint32_t*)&p23;
        }
        lA += sumA; lB += sumB;

        // O += P V (A frag i2 = S-frags {2i2, 2i2+1}; V frags via ldmatrix)
        uint32_t pa[4][4];
#pragma unroll
        for (int i2 = 0; i2 < 4; i2++) {
            pa[i2][0] = ph[2 * i2][0];     pa[i2][1] = ph[2 * i2][1];
            pa[i2][2] = ph[2 * i2 + 1][0]; pa[i2][3] = ph[2 * i2 + 1][1];
        }
#pragma unroll
        for (int j3 = 0; j3 < 8; j3++) {
            uint32_t base = vsb + p * KVBYTES + (uint32_t)(j3 * 8 * TLD) * 2 + lm_off;
            uint32_t bm[4];
            ldsm4(bm, base);
            mma16816(o[j3], pa[0], bm[0], bm[1]);
            mma16816(o[j3], pa[1], bm[2], bm[3]);
            ldsm4(bm, base + 64);
            mma16816(o[j3], pa[2], bm[0], bm[1]);
            mma16816(o[j3], pa[3], bm[2], bm[3]);
        }
        __syncthreads();
    }

    lA += __shfl_xor_sync(0xffffffffu, lA, 1);
    lA += __shfl_xor_sync(0xffffffffu, lA, 2);
    lB += __shfl_xor_sync(0xffffffffu, lB, 1);
    lB += __shfl_xor_sync(0xffffffffu, lB, 2);
    float rA = 1.0f / lA, rB = 1.0f / lB;

    float* obase = out + ((size_t)b * NQ + q0 + warp * 16) * DIM + h * HD;
#pragma unroll
    for (int j3 = 0; j3 < 8; j3++) {
        float2 vA = { o[j3][0] * rA, o[j3][1] * rA };
        float2 vB = { o[j3][2] * rB, o[j3][3] * rB };
        *(float2*)&obase[(size_t)group * DIM + j3 * 8 + tig * 2] = vA;
        *(float2*)&obase[(size_t)(group + 8) * DIM + j3 * 8 + tig * 2] = vB;
    }
}

// ---------------------------------------------------------------------------
extern "C" void kernel_launch(void* const* d_in, const int* in_sizes, int n_in,
                              void* d_out, int out_size)
{
    const float* x  = (const float*)d_in[0];
    const float* cx = (const float*)d_in[1];
    const float* Wq = (const float*)d_in[2];
    const float* Wk = (const float*)d_in[3];
    const float* Wv = (const float*)d_in[4];
    float* out = (float*)d_out;

    cudaFuncSetAttribute((const void*)proj_all,
                         cudaFuncAttributeMaxDynamicSharedMemorySize, PROJ_SMEM);

    conv_all<<<CONV_BLOCKS, 256>>>(x, cx, Wq, Wk, Wv);
    proj_all<<<1280, 256, PROJ_SMEM>>>();
    attn_fa<<<dim3(NQ / ATQ, NH, NB), 128>>>(out);
}

// round 12
// speedup vs baseline: 1.4319x; 1.1290x over previous
#include <cuda_runtime.h>
#include <cuda_fp16.h>
#include <cstdint>
#include <mma.h>
using namespace nvcuda;

#define DIM 2048
#define NH 32
#define HD 64
#define NB 2
#define NQ 4096
#define NKV 512

// -------- device scratch (allocation-free rule) --------
__device__ __half h_x [(size_t)NB * NQ  * DIM];
__device__ __half h_cx[(size_t)NB * NKV * DIM];
__device__ __half h_wq[(size_t)DIM * DIM];
__device__ __half h_wk[(size_t)DIM * DIM];        // gathered rows h*128+2d
__device__ __half h_wv[(size_t)DIM * DIM];        // gathered rows h*128+2d+1
__device__ __half g_q[(size_t)NB * NH * NQ  * HD]; // rmsnorm(q) * 0.125 * log2(e)
__device__ __half g_k[(size_t)NB * NH * NKV * HD];
__device__ __half g_v[(size_t)NB * NH * HD * NKV]; // (b,h,d,m) transposed

// ===========================================================================
// Fused conversion prepass — one launch (known good).
// ===========================================================================
#define CONV_BLOCKS 26624

__global__ __launch_bounds__(256) void conv_all(
    const float* __restrict__ x, const float* __restrict__ cx,
    const float* __restrict__ Wq, const float* __restrict__ Wk,
    const float* __restrict__ Wv)
{
    const int bid = blockIdx.x;
    const int t = threadIdx.x;
    if (bid < 22528) {
        const float* src;
        __half* dst;
        size_t i;
        if (bid < 16384)      { src = x;  dst = h_x;  i = ((size_t)bid * 256 + t) * 4; }
        else if (bid < 18432) { src = cx; dst = h_cx; i = ((size_t)(bid - 16384) * 256 + t) * 4; }
        else                  { src = Wq; dst = h_wq; i = ((size_t)(bid - 18432) * 256 + t) * 4; }
        float4 v = *(const float4*)&src[i];
        __half o[4] = { __float2half_rn(v.x), __float2half_rn(v.y),
                        __float2half_rn(v.z), __float2half_rn(v.w) };
        *(uint2*)&dst[i] = *(uint2*)o;
    } else {
        int i = bid - 22528;
        int j = i >> 1;
        int c = ((i & 1) * 256 + t) * 4;
        int h = j >> 6, d = j & 63;
        int g = h * 128 + 2 * d;
        const float* srcK = (g < DIM) ? (Wk + (size_t)g * DIM) : (Wv + (size_t)(g - DIM) * DIM);
        const float* srcV = (g + 1 < DIM) ? (Wk + (size_t)(g + 1) * DIM)
                                          : (Wv + (size_t)(g + 1 - DIM) * DIM);
        float4 vk = *(const float4*)&srcK[c];
        float4 vv = *(const float4*)&srcV[c];
        __half ok[4] = { __float2half_rn(vk.x), __float2half_rn(vk.y),
                         __float2half_rn(vk.z), __float2half_rn(vk.w) };
        __half ov[4] = { __float2half_rn(vv.x), __float2half_rn(vv.y),
                         __float2half_rn(vv.z), __float2half_rn(vv.w) };
        *(uint2*)&h_wk[(size_t)j * DIM + c] = *(uint2*)ok;
        *(uint2*)&h_wv[(size_t)j * DIM + c] = *(uint2*)ov;
    }
}

// common cp.async macros
#define CP16(d, s) asm volatile("cp.async.cg.shared.global [%0], [%1], 16;" :: "r"(d), "l"(s))
#define CP_COMMIT() asm volatile("cp.async.commit_group;" ::: "memory")
#define CP_WAIT(n)  asm volatile("cp.async.wait_group %0;" :: "n"(n) : "memory")

// GEMM tiling: K chunk 64 (32 mainloop iterations), row = 128 B data + 16 B pad
#define KC 64
#define KCP2 72                        // halves per smem row (144 B)
#define ROWB 144
#define CLD2 136
#define NCHUNK (DIM / KC)              // 32

#define BM 128
#define ABYTES (BM * ROWB)             // 18432
#define STAGE (2 * ABYTES)             // 36864 (A + B)
#define PROJ_SMEM (2 * STAGE)          // 73728 -> 2 CTAs/SM

// q scale: 1/8 (softmax) * log2(e) (for ex2-based exp)
#define QSCALE 0.18033688011112042f

// ===========================================================================
// Fused projection GEMM — one 1280-CTA launch; KC=64, 2-stage cp.async.
// ===========================================================================
__global__ __launch_bounds__(256, 2) void proj_all()
{
    extern __shared__ char smraw[];
    uint32_t sbase;
    asm("{ .reg .u64 t; cvta.to.shared.u64 t, %1; cvt.u32.u64 %0, t; }"
        : "=r"(sbase) : "l"(smraw));

    int mode, mt, nt;
    const __half *A, *Bm;
    {
        int bid = blockIdx.x;
        if (bid < 256) {
            int i = bid >> 1;
            mode = 1 + (bid & 1);
            mt = i & 7; nt = i >> 3;
            A = h_cx; Bm = (mode == 1) ? h_wk : h_wv;
        } else {
            int i = bid - 256;
            mode = 0;
            mt = i & 63; nt = i >> 6;
            A = h_x; Bm = h_wq;
        }
    }
    const int m0 = mt * BM;
    const int n0 = nt * BM;
    const int t = threadIdx.x;
    const int warp = t >> 5;
    const int wr = warp & 3;
    const int wc = warp >> 2;

    wmma::fragment<wmma::accumulator, 16, 16, 16, float> c[2][4];
#pragma unroll
    for (int i = 0; i < 2; i++)
#pragma unroll
        for (int j = 0; j < 4; j++) wmma::fill_fragment(c[i][j], 0.0f);

    // per-stage: 1024 A-chunks + 1024 B-chunks of 16 B -> 8 per thread
    const __half* gsrc[8];
    uint32_t doff[8];
#pragma unroll
    for (int j = 0; j < 8; j++) {
        int cidx = t + j * 256;
        if (cidx < 1024) {
            int r = cidx >> 3, sl = cidx & 7;
            gsrc[j] = A + (size_t)(m0 + r) * DIM + sl * 8;
            doff[j] = r * ROWB + sl * 16;
        } else {
            int r = (cidx - 1024) >> 3, sl = cidx & 7;
            gsrc[j] = Bm + (size_t)(n0 + r) * DIM + sl * 8;
            doff[j] = ABYTES + r * ROWB + sl * 16;
        }
    }

#define ISSUE(s, k0) do { \
        _Pragma("unroll") \
        for (int j = 0; j < 8; j++) \
            CP16(sbase + (s) * STAGE + doff[j], gsrc[j] + (k0)); \
        CP_COMMIT(); \
    } while (0)

    ISSUE(0, 0);

    for (int i = 0; i < NCHUNK; i++) {
        const int p = i & 1;
        if (i + 1 < NCHUNK) { ISSUE(p ^ 1, (i + 1) * KC); CP_WAIT(1); }
        else                { CP_WAIT(0); }
        __syncthreads();

        const __half* As = (const __half*)(smraw + p * STAGE);
        const __half* Bs = (const __half*)(smraw + p * STAGE + ABYTES);
#pragma unroll
        for (int ks = 0; ks < KC; ks += 16) {
            wmma::fragment<wmma::matrix_a, 16, 16, 16, __half, wmma::row_major> a0, a1;
            wmma::load_matrix_sync(a0, &As[(wr * 32) * KCP2 + ks], KCP2);
            wmma::load_matrix_sync(a1, &As[(wr * 32 + 16) * KCP2 + ks], KCP2);
#pragma unroll
            for (int nn = 0; nn < 4; nn++) {
                wmma::fragment<wmma::matrix_b, 16, 16, 16, __half, wmma::col_major> b;
                wmma::load_matrix_sync(b, &Bs[(wc * 64 + nn * 16) * KCP2 + ks], KCP2);
                wmma::mma_sync(c[0][nn], a0, b, c[0][nn]);
                wmma::mma_sync(c[1][nn], a1, b, c[1][nn]);
            }
        }
        __syncthreads();
    }

    // epilogue: stage C as half, per-head RMSNorm, write scratch
    __half* Cs = (__half*)smraw;   // BM x CLD2 halves = 34816 B <= PROJ_SMEM
#pragma unroll
    for (int i = 0; i < 2; i++)
#pragma unroll
        for (int nn = 0; nn < 4; nn++) {
            wmma::fragment<wmma::accumulator, 16, 16, 16, __half> ch;
#pragma unroll
            for (int e = 0; e < ch.num_elements; e++)
                ch.x[e] = __float2half_rn(c[i][nn].x[e]);
            wmma::store_matrix_sync(&Cs[(wr * 32 + i * 16) * CLD2 + wc * 64 + nn * 16],
                                    ch, CLD2, wmma::mem_row_major);
        }
    __syncthreads();

    __shared__ float sscale[BM * 2];
    {
        int row = t >> 1, g = t & 1;
        float s = 1.0f;
        if (mode != 2) {
            const __half* cr = &Cs[row * CLD2 + g * 64];
            float ss = 0.0f;
#pragma unroll
            for (int d = 0; d < 64; d++) { float v = __half2float(cr[d]); ss += v * v; }
            s = rsqrtf(ss * (1.0f / 64.0f) + 1e-6f);
            if (mode == 0) s *= QSCALE;
        }
        sscale[row * 2 + g] = s;
    }
    __syncthreads();

#pragma unroll
    for (int it = 0; it < 16; it++) {
        int f = t + it * 256;
        int row = f >> 5;
        int j = (f & 31) << 2;
        int g = j >> 6;
        int d = j & 63;
        int gi = m0 + row;
        int bb, n;
        if (mode == 0) { bb = gi >> 12; n = gi & 4095; }
        else           { bb = gi >> 9;  n = gi & 511;  }
        int h = (n0 >> 6) + g;
        float sc = sscale[row * 2 + g];
        const __half* cr = &Cs[row * CLD2 + j];
        __half o[4];
#pragma unroll
        for (int u = 0; u < 4; u++)
            o[u] = __float2half_rn(__half2float(cr[u]) * sc);
        if (mode == 2) {
#pragma unroll
            for (int u = 0; u < 4; u++)
                g_v[(((size_t)bb * NH + h) * HD + d + u) * NKV + n] = o[u];
        } else if (mode == 0) {
            *(uint2*)&g_q[(((size_t)bb * NH + h) * NQ + n) * HD + d] = *(uint2*)o;
        } else {
            *(uint2*)&g_k[(((size_t)bb * NH + h) * NKV + n) * HD + d] = *(uint2*)o;
        }
    }
}

// ===========================================================================
// FlashAttention attention, no-max softmax, ldmatrix.x4 (R11, known good).
// ===========================================================================
#define ATQ 64
#define KVT 64
#define TLD 72
#define KVBYTES (KVT * TLD * 2)   // 9216 per buffer

__device__ __forceinline__ void mma16816(float* c, const uint32_t* a,
                                         uint32_t b0, uint32_t b1)
{
    asm volatile(
        "mma.sync.aligned.m16n8k16.row.col.f32.f16.f16.f32 "
        "{%0,%1,%2,%3}, {%4,%5,%6,%7}, {%8,%9}, {%0,%1,%2,%3};"
        : "+f"(c[0]), "+f"(c[1]), "+f"(c[2]), "+f"(c[3])
        : "r"(a[0]), "r"(a[1]), "r"(a[2]), "r"(a[3]), "r"(b0), "r"(b1));
}

__device__ __forceinline__ void ldsm4(uint32_t* b, uint32_t addr)
{
    asm volatile("ldmatrix.sync.aligned.m8n8.x4.shared.b16 {%0,%1,%2,%3}, [%4];"
                 : "=r"(b[0]), "=r"(b[1]), "=r"(b[2]), "=r"(b[3]) : "r"(addr));
}

__device__ __forceinline__ float ex2(float x)
{
    float r;
    asm("ex2.approx.ftz.f32 %0, %1;" : "=f"(r) : "f"(x));
    return r;
}

__global__ __launch_bounds__(128, 4) void attn_fa(float* __restrict__ out)
{
    __shared__ __half Ks[2][KVT * TLD];
    __shared__ __half Vs[2][HD * TLD];

    const int t = threadIdx.x;
    const int warp = t >> 5, lane = t & 31;
    const int group = lane >> 2, tig = lane & 3;
    const int q0 = blockIdx.x * ATQ;
    const int h = blockIdx.y, b = blockIdx.z;

    const __half* qbase = g_q + (((size_t)b * NH + h) * NQ + q0 + warp * 16) * HD;
    const __half* kbase = g_k + ((size_t)b * NH + h) * NKV * HD;
    const __half* vtbase = g_v + ((size_t)b * NH + h) * HD * NKV;

    uint32_t ksb, vsb;
    asm("{ .reg .u64 u; cvta.to.shared.u64 u, %1; cvt.u32.u64 %0, u; }" : "=r"(ksb) : "l"(&Ks[0][0]));
    asm("{ .reg .u64 u; cvta.to.shared.u64 u, %1; cvt.u32.u64 %0, u; }" : "=r"(vsb) : "l"(&Vs[0][0]));

    const uint32_t lm_off = ((uint32_t)(lane & 7) * TLD + (uint32_t)(lane >> 3) * 8) * 2;

    int rr[4], cc[4];
#pragma unroll
    for (int it = 0; it < 4; it++) {
        int f = t + it * 128;
        rr[it] = f >> 3;
        cc[it] = (f & 7) * 8;
    }

#define AISSUE(kt, p) do { \
        _Pragma("unroll") \
        for (int it = 0; it < 4; it++) { \
            CP16(ksb + (p) * KVBYTES + (rr[it] * TLD + cc[it]) * 2, \
                 &kbase[((kt) * 64 + rr[it]) * HD + cc[it]]); \
            CP16(vsb + (p) * KVBYTES + (rr[it] * TLD + cc[it]) * 2, \
                 &vtbase[(size_t)rr[it] * NKV + (kt) * 64 + cc[it]]); \
        } \
        CP_COMMIT(); \
    } while (0)

    uint32_t qa[4][4];
    {
        const __half* qrA = qbase + group * HD;
        const __half* qrB = qbase + (group + 8) * HD;
#pragma unroll
        for (int i = 0; i < 4; i++) {
            qa[i][0] = *(const uint32_t*)&qrA[i * 16 + tig * 2];
            qa[i][1] = *(const uint32_t*)&qrB[i * 16 + tig * 2];
            qa[i][2] = *(const uint32_t*)&qrA[i * 16 + 8 + tig * 2];
            qa[i][3] = *(const uint32_t*)&qrB[i * 16 + 8 + tig * 2];
        }
    }

    AISSUE(0, 0);

    float o[8][4];
#pragma unroll
    for (int j = 0; j < 8; j++)
        o[j][0] = o[j][1] = o[j][2] = o[j][3] = 0.0f;
    float lA = 0.0f, lB = 0.0f;

    for (int kt = 0; kt < 8; kt++) {
        const int p = kt & 1;
        if (kt < 7) { AISSUE(kt + 1, p ^ 1); CP_WAIT(1); }
        else        { CP_WAIT(0); }
        __syncthreads();

        float s[8][4];
#pragma unroll
        for (int j = 0; j < 8; j++) {
            s[j][0] = s[j][1] = s[j][2] = s[j][3] = 0.0f;
            uint32_t base = ksb + p * KVBYTES + (uint32_t)(j * 8 * TLD) * 2 + lm_off;
            uint32_t bm[4];
            ldsm4(bm, base);
            mma16816(s[j], qa[0], bm[0], bm[1]);
            mma16816(s[j], qa[1], bm[2], bm[3]);
            ldsm4(bm, base + 64);
            mma16816(s[j], qa[2], bm[0], bm[1]);
            mma16816(s[j], qa[3], bm[2], bm[3]);
        }

        uint32_t ph[8][2];
        float sumA = 0.0f, sumB = 0.0f;
#pragma unroll
        for (int j = 0; j < 8; j++) {
            float e0 = ex2(s[j][0]);
            float e1 = ex2(s[j][1]);
            float e2 = ex2(s[j][2]);
            float e3 = ex2(s[j][3]);
            sumA += e0 + e1; sumB += e2 + e3;
            __half2 p01 = __floats2half2_rn(e0, e1);
            __half2 p23 = __floats2half2_rn(e2, e3);
            ph[j][0] = *(uint32_t*)&p01;
            ph[j][1] = *(uint32_t*)&p23;
        }
        lA += sumA; lB += sumB;

        uint32_t pa[4][4];
#pragma unroll
        for (int i2 = 0; i2 < 4; i2++) {
            pa[i2][0] = ph[2 * i2][0];     pa[i2][1] = ph[2 * i2][1];
            pa[i2][2] = ph[2 * i2 + 1][0]; pa[i2][3] = ph[2 * i2 + 1][1];
        }
#pragma unroll
        for (int j3 = 0; j3 < 8; j3++) {
            uint32_t base = vsb + p * KVBYTES + (uint32_t)(j3 * 8 * TLD) * 2 + lm_off;
            uint32_t bm[4];
            ldsm4(bm, base);
            mma16816(o[j3], pa[0], bm[0], bm[1]);
            mma16816(o[j3], pa[1], bm[2], bm[3]);
            ldsm4(bm, base + 64);
            mma16816(o[j3], pa[2], bm[0], bm[1]);
            mma16816(o[j3], pa[3], bm[2], bm[3]);
        }
        __syncthreads();
    }

    lA += __shfl_xor_sync(0xffffffffu, lA, 1);
    lA += __shfl_xor_sync(0xffffffffu, lA, 2);
    lB += __shfl_xor_sync(0xffffffffu, lB, 1);
    lB += __shfl_xor_sync(0xffffffffu, lB, 2);
    float rA = 1.0f / lA, rB = 1.0f / lB;

    float* obase = out + ((size_t)b * NQ + q0 + warp * 16) * DIM + h * HD;
#pragma unroll
    for (int j3 = 0; j3 < 8; j3++) {
        float2 vA = { o[j3][0] * rA, o[j3][1] * rA };
        float2 vB = { o[j3][2] * rB, o[j3][3] * rB };
        *(float2*)&obase[(size_t)group * DIM + j3 * 8 + tig * 2] = vA;
        *(float2*)&obase[(size_t)(group + 8) * DIM + j3 * 8 + tig * 2] = vB;
    }
}

// ---------------------------------------------------------------------------
extern "C" void kernel_launch(void* const* d_in, const int* in_sizes, int n_in,
                              void* d_out, int out_size)
{
    const float* x  = (const float*)d_in[0];
    const float* cx = (const float*)d_in[1];
    const float* Wq = (const float*)d_in[2];
    const float* Wk = (const float*)d_in[3];
    const float* Wv = (const float*)d_in[4];
    float* out = (float*)d_out;

    cudaFuncSetAttribute((const void*)proj_all,
                         cudaFuncAttributeMaxDynamicSharedMemorySize, PROJ_SMEM);

    conv_all<<<CONV_BLOCKS, 256>>>(x, cx, Wq, Wk, Wv);
    proj_all<<<1280, 256, PROJ_SMEM>>>();
    attn_fa<<<dim3(NQ / ATQ, NH, NB), 128>>>(out);
}